// round 1
// baseline (speedup 1.0000x reference)
#include <cuda_runtime.h>
#include <cuda_bf16.h>

#define DIM 256          // IN_DIM == OUT_DIM == 256
#define N_NODES_MAX 50000

// Scratch for hidden = x @ W  (no cudaMalloc allowed)
__device__ float g_hidden[N_NODES_MAX * DIM];

// ---------------------------------------------------------------------------
// Kernel 1: SGEMM  C[M,256] = A[M,256] @ B[256,256]
// 128x128 block tile, BK=16, 256 threads, 8x8 register tile per thread.
// ---------------------------------------------------------------------------
__global__ __launch_bounds__(256) void sgemm_kernel(const float* __restrict__ A,
                                                    const float* __restrict__ B,
                                                    float* __restrict__ C,
                                                    int M) {
    constexpr int K = DIM;
    constexpr int N = DIM;
    constexpr int BM = 128, BN = 128, BK = 16;

    __shared__ float As[BK][BM];   // transposed A tile
    __shared__ float Bs[BK][BN];

    const int tid = threadIdx.x;
    const int tr  = tid >> 4;      // 0..15
    const int tc  = tid & 15;      // 0..15
    const int blockM = blockIdx.y * BM;
    const int blockN = blockIdx.x * BN;

    float acc[8][8];
#pragma unroll
    for (int i = 0; i < 8; i++)
#pragma unroll
        for (int j = 0; j < 8; j++) acc[i][j] = 0.f;

    for (int k0 = 0; k0 < K; k0 += BK) {
        // Load A tile: 128x16 = 512 float4, 2 per thread, store transposed.
#pragma unroll
        for (int t = 0; t < 2; t++) {
            int idx  = tid * 2 + t;           // 0..511
            int row  = idx >> 2;              // 0..127
            int c4   = (idx & 3) * 4;         // 0,4,8,12
            int grow = blockM + row;
            float4 v = make_float4(0.f, 0.f, 0.f, 0.f);
            if (grow < M)
                v = *reinterpret_cast<const float4*>(&A[grow * K + k0 + c4]);
            As[c4 + 0][row] = v.x;
            As[c4 + 1][row] = v.y;
            As[c4 + 2][row] = v.z;
            As[c4 + 3][row] = v.w;
        }
        // Load B tile: 16x128 = 512 float4, 2 per thread.
#pragma unroll
        for (int t = 0; t < 2; t++) {
            int idx = tid * 2 + t;
            int row = idx >> 5;               // 0..15
            int col = (idx & 31) * 4;         // 0..124
            float4 v = *reinterpret_cast<const float4*>(&B[(k0 + row) * N + blockN + col]);
            *reinterpret_cast<float4*>(&Bs[row][col]) = v;
        }
        __syncthreads();

#pragma unroll
        for (int k = 0; k < BK; k++) {
            float a[8], bb[8];
#pragma unroll
            for (int i = 0; i < 8; i++) a[i] = As[k][tr * 8 + i];
#pragma unroll
            for (int j = 0; j < 8; j++) bb[j] = Bs[k][tc * 8 + j];
#pragma unroll
            for (int i = 0; i < 8; i++)
#pragma unroll
                for (int j = 0; j < 8; j++)
                    acc[i][j] = fmaf(a[i], bb[j], acc[i][j]);
        }
        __syncthreads();
    }

#pragma unroll
    for (int i = 0; i < 8; i++) {
        int grow = blockM + tr * 8 + i;
        if (grow < M) {
#pragma unroll
            for (int j4 = 0; j4 < 8; j4 += 4) {
                float4 v = make_float4(acc[i][j4], acc[i][j4 + 1],
                                       acc[i][j4 + 2], acc[i][j4 + 3]);
                *reinterpret_cast<float4*>(&C[grow * N + blockN + tc * 8 + j4]) = v;
            }
        }
    }
}

// ---------------------------------------------------------------------------
// Kernel 2: out[n, :] = b   (broadcast bias, float4 stores)
// ---------------------------------------------------------------------------
__global__ void init_out_kernel(float* __restrict__ out,
                                const float* __restrict__ b, int total4) {
    int i = blockIdx.x * blockDim.x + threadIdx.x;
    if (i < total4) {
        const float4* b4 = reinterpret_cast<const float4*>(b);
        reinterpret_cast<float4*>(out)[i] = b4[i & 63];   // 256 dims = 64 float4
    }
}

// ---------------------------------------------------------------------------
// Kernel 3: edge scatter. One warp per edge:
//   out[rows[e], :] += vals[e] * hidden[cols[e], :]
// Each lane handles 8 dims (2 float4 gathers + 8 atomicAdds).
// hidden and out both fit in L2 -> gathers + REDs are L2-resident.
// ---------------------------------------------------------------------------
__global__ __launch_bounds__(256) void spmm_edge_kernel(const int*   __restrict__ rows,
                                                        const int*   __restrict__ cols,
                                                        const float* __restrict__ vals,
                                                        const float* __restrict__ hidden,
                                                        float*       __restrict__ out,
                                                        int E) {
    int warpId = (blockIdx.x * blockDim.x + threadIdx.x) >> 5;
    int lane   = threadIdx.x & 31;
    if (warpId >= E) return;

    int   r = rows[warpId];
    int   c = cols[warpId];
    float v = vals[warpId];

    const float4* h4 = reinterpret_cast<const float4*>(hidden + (size_t)c * DIM);
    float*        o  = out + (size_t)r * DIM + lane * 8;

    float4 h0 = h4[lane * 2];
    float4 h1 = h4[lane * 2 + 1];

    atomicAdd(&o[0], v * h0.x);
    atomicAdd(&o[1], v * h0.y);
    atomicAdd(&o[2], v * h0.z);
    atomicAdd(&o[3], v * h0.w);
    atomicAdd(&o[4], v * h1.x);
    atomicAdd(&o[5], v * h1.y);
    atomicAdd(&o[6], v * h1.z);
    atomicAdd(&o[7], v * h1.w);
}

// ---------------------------------------------------------------------------
// Launch
// inputs (metadata order): x[50000*256] f32, adj_rows[E] i32, adj_cols[E] i32,
//                          adj_vals[E] f32, W[256*256] f32, b[256] f32
// ---------------------------------------------------------------------------
extern "C" void kernel_launch(void* const* d_in, const int* in_sizes, int n_in,
                              void* d_out, int out_size) {
    const float* x        = (const float*)d_in[0];
    const int*   adj_rows = (const int*)  d_in[1];
    const int*   adj_cols = (const int*)  d_in[2];
    const float* adj_vals = (const float*)d_in[3];
    const float* W        = (const float*)d_in[4];
    const float* b        = (const float*)d_in[5];
    float*       out      = (float*)d_out;

    const int M = in_sizes[0] / DIM;   // 50000 nodes
    const int E = in_sizes[1];         // 800000 edges

    float* hidden;
    cudaGetSymbolAddress((void**)&hidden, g_hidden);

    // 1) hidden = x @ W
    dim3 gemmGrid(DIM / 128, (M + 127) / 128);
    sgemm_kernel<<<gemmGrid, 256>>>(x, W, hidden, M);

    // 2) out = broadcast(b)
    int total4 = M * (DIM / 4);
    init_out_kernel<<<(total4 + 255) / 256, 256>>>(out, b, total4);

    // 3) out[rows] += vals * hidden[cols]
    long long threadsNeeded = (long long)E * 32;
    int blocks = (int)((threadsNeeded + 255) / 256);
    spmm_edge_kernel<<<blocks, 256>>>(adj_rows, adj_cols, adj_vals, hidden, out, E);
}

// round 2
// speedup vs baseline: 2.8391x; 2.8391x over previous
#include <cuda_runtime.h>
#include <cuda_bf16.h>

#define DIM 256
#define N_NODES_MAX 50000
#define N_EDGES_MAX 800000

// ----- scratch (__device__ globals; no cudaMalloc allowed) -----
__device__ float g_hidden[N_NODES_MAX * DIM];           // x @ W
__device__ int   g_counts[N_NODES_MAX];                 // per-row edge counts
__device__ int   g_row_ptr[N_NODES_MAX + 1];            // CSR row pointers
__device__ int   g_cursor[N_NODES_MAX];                 // scatter cursors
__device__ int   g_csr_col[N_EDGES_MAX];                // CSR col index (src node)
__device__ float g_csr_val[N_EDGES_MAX];                // CSR edge value

// ---------------------------------------------------------------------------
// Kernel 1: SGEMM  C[M,256] = A[M,256] @ B[256,256]
// 128x128 tile, BK=16, 256 threads, 8x8 register tile. (unchanged from R0)
// ---------------------------------------------------------------------------
__global__ __launch_bounds__(256) void sgemm_kernel(const float* __restrict__ A,
                                                    const float* __restrict__ B,
                                                    float* __restrict__ C,
                                                    int M) {
    constexpr int K = DIM;
    constexpr int N = DIM;
    constexpr int BM = 128, BN = 128, BK = 16;

    __shared__ float As[BK][BM];
    __shared__ float Bs[BK][BN];

    const int tid = threadIdx.x;
    const int tr  = tid >> 4;
    const int tc  = tid & 15;
    const int blockM = blockIdx.y * BM;
    const int blockN = blockIdx.x * BN;

    float acc[8][8];
#pragma unroll
    for (int i = 0; i < 8; i++)
#pragma unroll
        for (int j = 0; j < 8; j++) acc[i][j] = 0.f;

    for (int k0 = 0; k0 < K; k0 += BK) {
#pragma unroll
        for (int t = 0; t < 2; t++) {
            int idx  = tid * 2 + t;
            int row  = idx >> 2;
            int c4   = (idx & 3) * 4;
            int grow = blockM + row;
            float4 v = make_float4(0.f, 0.f, 0.f, 0.f);
            if (grow < M)
                v = *reinterpret_cast<const float4*>(&A[grow * K + k0 + c4]);
            As[c4 + 0][row] = v.x;
            As[c4 + 1][row] = v.y;
            As[c4 + 2][row] = v.z;
            As[c4 + 3][row] = v.w;
        }
#pragma unroll
        for (int t = 0; t < 2; t++) {
            int idx = tid * 2 + t;
            int row = idx >> 5;
            int col = (idx & 31) * 4;
            float4 v = *reinterpret_cast<const float4*>(&B[(k0 + row) * N + blockN + col]);
            *reinterpret_cast<float4*>(&Bs[row][col]) = v;
        }
        __syncthreads();

#pragma unroll
        for (int k = 0; k < BK; k++) {
            float a[8], bb[8];
#pragma unroll
            for (int i = 0; i < 8; i++) a[i] = As[k][tr * 8 + i];
#pragma unroll
            for (int j = 0; j < 8; j++) bb[j] = Bs[k][tc * 8 + j];
#pragma unroll
            for (int i = 0; i < 8; i++)
#pragma unroll
                for (int j = 0; j < 8; j++)
                    acc[i][j] = fmaf(a[i], bb[j], acc[i][j]);
        }
        __syncthreads();
    }

#pragma unroll
    for (int i = 0; i < 8; i++) {
        int grow = blockM + tr * 8 + i;
        if (grow < M) {
#pragma unroll
            for (int j4 = 0; j4 < 8; j4 += 4) {
                float4 v = make_float4(acc[i][j4], acc[i][j4 + 1],
                                       acc[i][j4 + 2], acc[i][j4 + 3]);
                *reinterpret_cast<float4*>(&C[grow * N + blockN + tc * 8 + j4]) = v;
            }
        }
    }
}

// ---------------------------------------------------------------------------
// CSR build step 1: histogram of destination rows (int atomics, spread)
// ---------------------------------------------------------------------------
__global__ void hist_kernel(const int* __restrict__ rows, int* __restrict__ counts, int E) {
    int i = blockIdx.x * blockDim.x + threadIdx.x;
    if (i < E) atomicAdd(&counts[rows[i]], 1);
}

// ---------------------------------------------------------------------------
// CSR build step 2: single-block exclusive scan of counts -> row_ptr, cursor
// 1024 threads, each owns a contiguous chunk; Hillis-Steele on block partials.
// ---------------------------------------------------------------------------
__global__ __launch_bounds__(1024) void scan_kernel(const int* __restrict__ counts,
                                                    int* __restrict__ row_ptr,
                                                    int* __restrict__ cursor,
                                                    int M) {
    __shared__ int s_sums[1024];
    const int t = threadIdx.x;
    const int chunk = (M + 1023) / 1024;
    const int begin = t * chunk;
    const int end   = min(begin + chunk, M);

    int sum = 0;
    for (int i = begin; i < end; i++) sum += counts[i];
    s_sums[t] = sum;
    __syncthreads();

#pragma unroll
    for (int off = 1; off < 1024; off <<= 1) {
        int v = (t >= off) ? s_sums[t - off] : 0;
        __syncthreads();
        s_sums[t] += v;
        __syncthreads();
    }

    int excl = (t == 0) ? 0 : s_sums[t - 1];
    for (int i = begin; i < end; i++) {
        row_ptr[i] = excl;
        cursor[i]  = excl;
        excl += counts[i];
    }
    if (t == 1023) row_ptr[M] = s_sums[1023];
}

// ---------------------------------------------------------------------------
// CSR build step 3: scatter edges into CSR slots (col + val directly)
// ---------------------------------------------------------------------------
__global__ void scatter_kernel(const int* __restrict__ rows,
                               const int* __restrict__ cols,
                               const float* __restrict__ vals,
                               int*   __restrict__ cursor,
                               int*   __restrict__ csr_col,
                               float* __restrict__ csr_val,
                               int E) {
    int i = blockIdx.x * blockDim.x + threadIdx.x;
    if (i < E) {
        int r   = rows[i];
        int pos = atomicAdd(&cursor[r], 1);
        csr_col[pos] = cols[i];
        csr_val[pos] = vals[i];
    }
}

// ---------------------------------------------------------------------------
// Kernel 5: CSR SpMM + bias. One block per dest node; thread t owns dim t.
// Edge metadata staged through smem; gathers are coalesced 1KB rows (L2-hit).
// Single register accumulator, single store — zero float atomics.
// ---------------------------------------------------------------------------
#define STAGE 128
__global__ __launch_bounds__(256) void spmm_csr_kernel(const int*   __restrict__ row_ptr,
                                                       const int*   __restrict__ csr_col,
                                                       const float* __restrict__ csr_val,
                                                       const float* __restrict__ hidden,
                                                       const float* __restrict__ b,
                                                       float*       __restrict__ out,
                                                       int M) {
    __shared__ int   s_col[STAGE];
    __shared__ float s_val[STAGE];

    const int n = blockIdx.x;
    const int t = threadIdx.x;
    const int s = row_ptr[n];
    const int e = row_ptr[n + 1];

    float acc = 0.f;

    for (int base = s; base < e; base += STAGE) {
        int cnt = min(STAGE, e - base);
        if (t < cnt) {
            s_col[t] = csr_col[base + t];
            s_val[t] = csr_val[base + t];
        }
        __syncthreads();

        int j = 0;
        // 4-wide unrolled body: 4 independent L2 gathers in flight per thread
        for (; j + 3 < cnt; j += 4) {
            float h0 = hidden[(size_t)s_col[j]     * DIM + t];
            float h1 = hidden[(size_t)s_col[j + 1] * DIM + t];
            float h2 = hidden[(size_t)s_col[j + 2] * DIM + t];
            float h3 = hidden[(size_t)s_col[j + 3] * DIM + t];
            acc = fmaf(s_val[j],     h0, acc);
            acc = fmaf(s_val[j + 1], h1, acc);
            acc = fmaf(s_val[j + 2], h2, acc);
            acc = fmaf(s_val[j + 3], h3, acc);
        }
        for (; j < cnt; j++)
            acc = fmaf(s_val[j], hidden[(size_t)s_col[j] * DIM + t], acc);
        __syncthreads();
    }

    out[(size_t)n * DIM + t] = acc + b[t];
}

// ---------------------------------------------------------------------------
// Launch
// ---------------------------------------------------------------------------
extern "C" void kernel_launch(void* const* d_in, const int* in_sizes, int n_in,
                              void* d_out, int out_size) {
    const float* x        = (const float*)d_in[0];
    const int*   adj_rows = (const int*)  d_in[1];
    const int*   adj_cols = (const int*)  d_in[2];
    const float* adj_vals = (const float*)d_in[3];
    const float* W        = (const float*)d_in[4];
    const float* b        = (const float*)d_in[5];
    float*       out      = (float*)d_out;

    const int M = in_sizes[0] / DIM;   // 50000
    const int E = in_sizes[1];         // 800000

    float *hidden, *csr_val;
    int *counts, *row_ptr, *cursor, *csr_col;
    cudaGetSymbolAddress((void**)&hidden,  g_hidden);
    cudaGetSymbolAddress((void**)&counts,  g_counts);
    cudaGetSymbolAddress((void**)&row_ptr, g_row_ptr);
    cudaGetSymbolAddress((void**)&cursor,  g_cursor);
    cudaGetSymbolAddress((void**)&csr_col, g_csr_col);
    cudaGetSymbolAddress((void**)&csr_val, g_csr_val);

    // 1) hidden = x @ W
    dim3 gemmGrid(DIM / 128, (M + 127) / 128);
    sgemm_kernel<<<gemmGrid, 256>>>(x, W, hidden, M);

    // 2) CSR build (independent of GEMM; small kernels)
    cudaMemsetAsync(counts, 0, (size_t)M * sizeof(int));
    hist_kernel<<<(E + 255) / 256, 256>>>(adj_rows, counts, E);
    scan_kernel<<<1, 1024>>>(counts, row_ptr, cursor, M);
    scatter_kernel<<<(E + 255) / 256, 256>>>(adj_rows, adj_cols, adj_vals,
                                             cursor, csr_col, csr_val, E);

    // 3) out = adj @ hidden + b   (no float atomics)
    spmm_csr_kernel<<<M, 256>>>(row_ptr, csr_col, csr_val, hidden, b, out, M);
}

// round 4
// speedup vs baseline: 4.3559x; 1.5343x over previous
#include <cuda_runtime.h>
#include <cuda_bf16.h>
#include <cstdint>

#define DIM 256
#define N_NODES_MAX 50000
#define N_EDGES_MAX 800000

// ----- scratch (__device__ globals; no cudaMalloc allowed) -----
__device__ float          g_hidden[N_NODES_MAX * DIM];   // x @ W
__device__ __nv_bfloat16  g_WT_hi[DIM * DIM];            // W^T hi split (WT[n][k])
__device__ __nv_bfloat16  g_WT_lo[DIM * DIM];            // W^T lo split
__device__ int            g_counts[N_NODES_MAX];
__device__ int            g_row_ptr[N_NODES_MAX + 1];
__device__ int            g_cursor[N_NODES_MAX];
__device__ int            g_csr_col[N_EDGES_MAX];
__device__ float          g_csr_val[N_EDGES_MAX];

// ===========================================================================
// Kernel 0: W^T + bf16 hi/lo split.  WT[n][k] = W[k][n]
// ===========================================================================
__global__ void wt_convert_kernel(const float* __restrict__ W,
                                  __nv_bfloat16* __restrict__ wt_hi,
                                  __nv_bfloat16* __restrict__ wt_lo) {
    int k = blockIdx.x;     // in_dim
    int n = threadIdx.x;    // out_dim
    float v = W[k * DIM + n];
    __nv_bfloat16 h = __float2bfloat16_rn(v);
    __nv_bfloat16 l = __float2bfloat16_rn(v - __bfloat162float(h));
    wt_hi[n * DIM + k] = h;
    wt_lo[n * DIM + k] = l;
}

// ===========================================================================
// Kernel 1: mma.sync bf16x2-split GEMM  hidden[M,256] = x[M,256] @ W[256,256]
//   C = Ahi*Bhi + Ahi*Blo + Alo*Bhi   (fp32 accum, residual ~2^-16)
// Block: 256 thr = 8 warps (4 M x 2 N), block tile 128x64, warp tile 32x32.
// B (=W^T) resident in smem for the full K=256; A converted+staged per K=64.
// ===========================================================================
#define SA 72     // A smem row stride in bf16 (64 + 8 pad)
#define SB 264    // B smem row stride in bf16 (256 + 8 pad)
#define A_HI_OFF 0
#define A_LO_OFF (128 * SA)
#define B_HI_OFF (2 * 128 * SA)
#define B_LO_OFF (2 * 128 * SA + 64 * SB)
#define GEMM_SMEM_BYTES ((2 * 128 * SA + 2 * 64 * SB) * 2)   // 104448

__device__ __forceinline__ void mma16816(float* c, const uint32_t* a, const uint32_t* b) {
    asm volatile(
        "mma.sync.aligned.m16n8k16.row.col.f32.bf16.bf16.f32 "
        "{%0,%1,%2,%3}, {%4,%5,%6,%7}, {%8,%9}, {%0,%1,%2,%3};"
        : "+f"(c[0]), "+f"(c[1]), "+f"(c[2]), "+f"(c[3])
        : "r"(a[0]), "r"(a[1]), "r"(a[2]), "r"(a[3]), "r"(b[0]), "r"(b[1]));
}

__global__ __launch_bounds__(256, 1) void gemm_mma_kernel(
        const float* __restrict__ x,
        const __nv_bfloat16* __restrict__ wt_hi,
        const __nv_bfloat16* __restrict__ wt_lo,
        float* __restrict__ hidden, int M) {
    extern __shared__ __nv_bfloat16 sm[];

    const int tid  = threadIdx.x;
    const int warp = tid >> 5;
    const int lane = tid & 31;
    const int gid  = lane >> 2;   // 0..7
    const int tig  = lane & 3;    // 0..3
    const int wm   = warp >> 1;   // 0..3  (M position)
    const int wn   = warp & 1;    // 0..1  (N position)
    const int blockM = blockIdx.y * 128;
    const int blockN = blockIdx.x * 64;

    // ---- load B tiles (full K) : 64 rows x 256 k, hi + lo ----
#pragma unroll
    for (int t = 0; t < 8; t++) {
        int idx = tid + t * 256;          // 0..2047
        int n = idx >> 5;                 // 0..63
        int j = idx & 31;                 // 8-bf16 group along k
        *reinterpret_cast<uint4*>(&sm[B_HI_OFF + n * SB + j * 8]) =
            *reinterpret_cast<const uint4*>(&wt_hi[(size_t)(blockN + n) * DIM + j * 8]);
        *reinterpret_cast<uint4*>(&sm[B_LO_OFF + n * SB + j * 8]) =
            *reinterpret_cast<const uint4*>(&wt_lo[(size_t)(blockN + n) * DIM + j * 8]);
    }

    float c[2][4][4];
#pragma unroll
    for (int f = 0; f < 2; f++)
#pragma unroll
        for (int g = 0; g < 4; g++)
#pragma unroll
            for (int q = 0; q < 4; q++) c[f][g][q] = 0.f;

    for (int kc = 0; kc < 4; kc++) {
        // ---- stage A chunk: x[blockM..+128, kc*64..+64] fp32 -> bf16 hi/lo ----
        __syncthreads();   // protect previous chunk's reads
#pragma unroll
        for (int t = 0; t < 8; t++) {
            int idx = tid + t * 256;      // 0..2047 float4 slots
            int row = idx >> 4;           // 0..127
            int c4  = idx & 15;           // float4 within 64-k chunk
            float4 v = make_float4(0.f, 0.f, 0.f, 0.f);
            if (blockM + row < M)
                v = *reinterpret_cast<const float4*>(
                        &x[(size_t)(blockM + row) * DIM + kc * 64 + c4 * 4]);
            __nv_bfloat16 h0 = __float2bfloat16_rn(v.x);
            __nv_bfloat16 h1 = __float2bfloat16_rn(v.y);
            __nv_bfloat16 h2 = __float2bfloat16_rn(v.z);
            __nv_bfloat16 h3 = __float2bfloat16_rn(v.w);
            __nv_bfloat16 l0 = __float2bfloat16_rn(v.x - __bfloat162float(h0));
            __nv_bfloat16 l1 = __float2bfloat16_rn(v.y - __bfloat162float(h1));
            __nv_bfloat16 l2 = __float2bfloat16_rn(v.z - __bfloat162float(h2));
            __nv_bfloat16 l3 = __float2bfloat16_rn(v.w - __bfloat162float(h3));
            uint2 hp = make_uint2(
                ((uint32_t)__bfloat16_as_ushort(h1) << 16) | __bfloat16_as_ushort(h0),
                ((uint32_t)__bfloat16_as_ushort(h3) << 16) | __bfloat16_as_ushort(h2));
            uint2 lp = make_uint2(
                ((uint32_t)__bfloat16_as_ushort(l1) << 16) | __bfloat16_as_ushort(l0),
                ((uint32_t)__bfloat16_as_ushort(l3) << 16) | __bfloat16_as_ushort(l2));
            *reinterpret_cast<uint2*>(&sm[A_HI_OFF + row * SA + c4 * 4]) = hp;
            *reinterpret_cast<uint2*>(&sm[A_LO_OFF + row * SA + c4 * 4]) = lp;
        }
        __syncthreads();

        // ---- MMA over this chunk: 4 k-steps of 16 ----
#pragma unroll
        for (int ks = 0; ks < 4; ks++) {
            const int kb = ks * 16;
            uint32_t a_hi[2][4], a_lo[2][4], b_hi[4][2], b_lo[4][2];
#pragma unroll
            for (int f = 0; f < 2; f++) {
                int r0 = wm * 32 + f * 16;
                a_hi[f][0] = *reinterpret_cast<const uint32_t*>(&sm[A_HI_OFF + (r0 + gid)     * SA + kb + 2 * tig]);
                a_hi[f][1] = *reinterpret_cast<const uint32_t*>(&sm[A_HI_OFF + (r0 + gid + 8) * SA + kb + 2 * tig]);
                a_hi[f][2] = *reinterpret_cast<const uint32_t*>(&sm[A_HI_OFF + (r0 + gid)     * SA + kb + 2 * tig + 8]);
                a_hi[f][3] = *reinterpret_cast<const uint32_t*>(&sm[A_HI_OFF + (r0 + gid + 8) * SA + kb + 2 * tig + 8]);
                a_lo[f][0] = *reinterpret_cast<const uint32_t*>(&sm[A_LO_OFF + (r0 + gid)     * SA + kb + 2 * tig]);
                a_lo[f][1] = *reinterpret_cast<const uint32_t*>(&sm[A_LO_OFF + (r0 + gid + 8) * SA + kb + 2 * tig]);
                a_lo[f][2] = *reinterpret_cast<const uint32_t*>(&sm[A_LO_OFF + (r0 + gid)     * SA + kb + 2 * tig + 8]);
                a_lo[f][3] = *reinterpret_cast<const uint32_t*>(&sm[A_LO_OFF + (r0 + gid + 8) * SA + kb + 2 * tig + 8]);
            }
#pragma unroll
            for (int g = 0; g < 4; g++) {
                int n0 = wn * 32 + g * 8;
                int kk = kc * 64 + kb + 2 * tig;
                b_hi[g][0] = *reinterpret_cast<const uint32_t*>(&sm[B_HI_OFF + (n0 + gid) * SB + kk]);
                b_hi[g][1] = *reinterpret_cast<const uint32_t*>(&sm[B_HI_OFF + (n0 + gid) * SB + kk + 8]);
                b_lo[g][0] = *reinterpret_cast<const uint32_t*>(&sm[B_LO_OFF + (n0 + gid) * SB + kk]);
                b_lo[g][1] = *reinterpret_cast<const uint32_t*>(&sm[B_LO_OFF + (n0 + gid) * SB + kk + 8]);
            }
#pragma unroll
            for (int f = 0; f < 2; f++)
#pragma unroll
                for (int g = 0; g < 4; g++) {
                    mma16816(c[f][g], a_hi[f], b_hi[g]);
                    mma16816(c[f][g], a_hi[f], b_lo[g]);
                    mma16816(c[f][g], a_lo[f], b_hi[g]);
                }
        }
    }

    // ---- epilogue: fragments -> hidden (float2 stores) ----
#pragma unroll
    for (int f = 0; f < 2; f++) {
#pragma unroll
        for (int g = 0; g < 4; g++) {
            int row = blockM + wm * 32 + f * 16 + gid;
            int col = blockN + wn * 32 + g * 8 + 2 * tig;
            if (row < M)
                *reinterpret_cast<float2*>(&hidden[(size_t)row * DIM + col]) =
                    make_float2(c[f][g][0], c[f][g][1]);
            if (row + 8 < M)
                *reinterpret_cast<float2*>(&hidden[(size_t)(row + 8) * DIM + col]) =
                    make_float2(c[f][g][2], c[f][g][3]);
        }
    }
}

// ===========================================================================
// CSR build
// ===========================================================================
__global__ void hist_kernel(const int* __restrict__ rows, int* __restrict__ counts, int E) {
    int i = blockIdx.x * blockDim.x + threadIdx.x;
    if (i < E) atomicAdd(&counts[rows[i]], 1);
}

__global__ __launch_bounds__(1024) void scan_kernel(const int* __restrict__ counts,
                                                    int* __restrict__ row_ptr,
                                                    int* __restrict__ cursor,
                                                    int M) {
    __shared__ int s_sums[1024];
    const int t = threadIdx.x;
    const int chunk = (M + 1023) / 1024;
    const int begin = t * chunk;
    const int end   = min(begin + chunk, M);

    int sum = 0;
    for (int i = begin; i < end; i++) sum += counts[i];
    s_sums[t] = sum;
    __syncthreads();

#pragma unroll
    for (int off = 1; off < 1024; off <<= 1) {
        int v = (t >= off) ? s_sums[t - off] : 0;
        __syncthreads();
        s_sums[t] += v;
        __syncthreads();
    }

    int excl = (t == 0) ? 0 : s_sums[t - 1];
    for (int i = begin; i < end; i++) {
        row_ptr[i] = excl;
        cursor[i]  = excl;
        excl += counts[i];
    }
    if (t == 1023) row_ptr[M] = s_sums[1023];
}

__global__ void scatter_kernel(const int* __restrict__ rows,
                               const int* __restrict__ cols,
                               const float* __restrict__ vals,
                               int*   __restrict__ cursor,
                               int*   __restrict__ csr_col,
                               float* __restrict__ csr_val,
                               int E) {
    int i = blockIdx.x * blockDim.x + threadIdx.x;
    if (i < E) {
        int r   = rows[i];
        int pos = atomicAdd(&cursor[r], 1);
        csr_col[pos] = cols[i];
        csr_val[pos] = vals[i];
    }
}

// ===========================================================================
// SpMM: warp per destination row. Lane owns 8 dims as two float4 slots
// (cols lane*4 and 128+lane*4). Edge (col,val) batched 32-wide, broadcast
// via shuffle; 2-edge unroll for L2 MLP. Zero atomics, zero __syncthreads.
// ===========================================================================
__global__ __launch_bounds__(256) void spmm_warp_kernel(const int*   __restrict__ row_ptr,
                                                        const int*   __restrict__ csr_col,
                                                        const float* __restrict__ csr_val,
                                                        const float* __restrict__ hidden,
                                                        const float* __restrict__ b,
                                                        float*       __restrict__ out,
                                                        int M) {
    const int w    = (blockIdx.x * blockDim.x + threadIdx.x) >> 5;
    const int lane = threadIdx.x & 31;
    if (w >= M) return;

    const int s = row_ptr[w];
    const int e = row_ptr[w + 1];

    float4 acc0 = make_float4(0.f, 0.f, 0.f, 0.f);
    float4 acc1 = make_float4(0.f, 0.f, 0.f, 0.f);

    for (int base = s; base < e; base += 32) {
        int   i = base + lane;
        int   cc = 0;
        float vv = 0.f;
        if (i < e) { cc = csr_col[i]; vv = csr_val[i]; }
        int cnt = min(32, e - base);

        int j = 0;
        for (; j + 1 < cnt; j += 2) {
            int   c0 = __shfl_sync(0xffffffffu, cc, j);
            float v0 = __shfl_sync(0xffffffffu, vv, j);
            int   c1 = __shfl_sync(0xffffffffu, cc, j + 1);
            float v1 = __shfl_sync(0xffffffffu, vv, j + 1);
            const float4* h0 = reinterpret_cast<const float4*>(hidden + (size_t)c0 * DIM);
            const float4* h1 = reinterpret_cast<const float4*>(hidden + (size_t)c1 * DIM);
            float4 p0 = h0[lane], p1 = h0[lane + 32];
            float4 q0 = h1[lane], q1 = h1[lane + 32];
            acc0.x = fmaf(v0, p0.x, acc0.x); acc0.y = fmaf(v0, p0.y, acc0.y);
            acc0.z = fmaf(v0, p0.z, acc0.z); acc0.w = fmaf(v0, p0.w, acc0.w);
            acc1.x = fmaf(v0, p1.x, acc1.x); acc1.y = fmaf(v0, p1.y, acc1.y);
            acc1.z = fmaf(v0, p1.z, acc1.z); acc1.w = fmaf(v0, p1.w, acc1.w);
            acc0.x = fmaf(v1, q0.x, acc0.x); acc0.y = fmaf(v1, q0.y, acc0.y);
            acc0.z = fmaf(v1, q0.z, acc0.z); acc0.w = fmaf(v1, q0.w, acc0.w);
            acc1.x = fmaf(v1, q1.x, acc1.x); acc1.y = fmaf(v1, q1.y, acc1.y);
            acc1.z = fmaf(v1, q1.z, acc1.z); acc1.w = fmaf(v1, q1.w, acc1.w);
        }
        if (j < cnt) {
            int   c0 = __shfl_sync(0xffffffffu, cc, j);
            float v0 = __shfl_sync(0xffffffffu, vv, j);
            const float4* h0 = reinterpret_cast<const float4*>(hidden + (size_t)c0 * DIM);
            float4 p0 = h0[lane], p1 = h0[lane + 32];
            acc0.x = fmaf(v0, p0.x, acc0.x); acc0.y = fmaf(v0, p0.y, acc0.y);
            acc0.z = fmaf(v0, p0.z, acc0.z); acc0.w = fmaf(v0, p0.w, acc0.w);
            acc1.x = fmaf(v0, p1.x, acc1.x); acc1.y = fmaf(v0, p1.y, acc1.y);
            acc1.z = fmaf(v0, p1.z, acc1.z); acc1.w = fmaf(v0, p1.w, acc1.w);
        }
    }

    const float4* b4 = reinterpret_cast<const float4*>(b);
    float4 bb0 = b4[lane], bb1 = b4[lane + 32];
    float4* o = reinterpret_cast<float4*>(out + (size_t)w * DIM);
    o[lane]      = make_float4(acc0.x + bb0.x, acc0.y + bb0.y, acc0.z + bb0.z, acc0.w + bb0.w);
    o[lane + 32] = make_float4(acc1.x + bb1.x, acc1.y + bb1.y, acc1.z + bb1.z, acc1.w + bb1.w);
}

// ===========================================================================
// Launch
// ===========================================================================
extern "C" void kernel_launch(void* const* d_in, const int* in_sizes, int n_in,
                              void* d_out, int out_size) {
    const float* x        = (const float*)d_in[0];
    const int*   adj_rows = (const int*)  d_in[1];
    const int*   adj_cols = (const int*)  d_in[2];
    const float* adj_vals = (const float*)d_in[3];
    const float* W        = (const float*)d_in[4];
    const float* b        = (const float*)d_in[5];
    float*       out      = (float*)d_out;

    const int M = in_sizes[0] / DIM;   // 50000
    const int E = in_sizes[1];         // 800000

    float *hidden, *csr_val;
    __nv_bfloat16 *wt_hi, *wt_lo;
    int *counts, *row_ptr, *cursor, *csr_col;
    cudaGetSymbolAddress((void**)&hidden,  g_hidden);
    cudaGetSymbolAddress((void**)&wt_hi,   g_WT_hi);
    cudaGetSymbolAddress((void**)&wt_lo,   g_WT_lo);
    cudaGetSymbolAddress((void**)&counts,  g_counts);
    cudaGetSymbolAddress((void**)&row_ptr, g_row_ptr);
    cudaGetSymbolAddress((void**)&cursor,  g_cursor);
    cudaGetSymbolAddress((void**)&csr_col, g_csr_col);
    cudaGetSymbolAddress((void**)&csr_val, g_csr_val);

    // 0) split-transpose W
    wt_convert_kernel<<<DIM, DIM>>>(W, wt_hi, wt_lo);

    // 1) hidden = x @ W  (mma.sync bf16x2)
    static bool attr_set = false;
    if (!attr_set) {
        cudaFuncSetAttribute(gemm_mma_kernel,
                             cudaFuncAttributeMaxDynamicSharedMemorySize, GEMM_SMEM_BYTES);
        attr_set = true;
    }
    dim3 gemmGrid(DIM / 64, (M + 127) / 128);
    gemm_mma_kernel<<<gemmGrid, 256, GEMM_SMEM_BYTES>>>(x, wt_hi, wt_lo, hidden, M);

    // 2) CSR build
    cudaMemsetAsync(counts, 0, (size_t)M * sizeof(int));
    hist_kernel<<<(E + 255) / 256, 256>>>(adj_rows, counts, E);
    scan_kernel<<<1, 1024>>>(counts, row_ptr, cursor, M);
    scatter_kernel<<<(E + 255) / 256, 256>>>(adj_rows, adj_cols, adj_vals,
                                             cursor, csr_col, csr_val, E);

    // 3) out = adj @ hidden + b  (warp per row)
    spmm_warp_kernel<<<(M * 32 + 255) / 256, 256>>>(row_ptr, csr_col, csr_val,
                                                    hidden, b, out, M);
}

// round 5
// speedup vs baseline: 6.1656x; 1.4155x over previous
#include <cuda_runtime.h>
#include <cuda_bf16.h>
#include <cuda_fp16.h>
#include <cstdint>

#define DIM 256
#define N_NODES_MAX 50000
#define N_EDGES_MAX 800000
#define SCAN_NB ((N_NODES_MAX + 255) / 256)   // 196

// ----- scratch (__device__ globals; no cudaMalloc allowed) -----
__device__ __half         g_hidden_h[N_NODES_MAX * DIM]; // x @ W (fp16)
__device__ __nv_bfloat16  g_WT_hi[DIM * DIM];            // W^T hi split (WT[n][k])
__device__ __nv_bfloat16  g_WT_lo[DIM * DIM];            // W^T lo split
__device__ int            g_counts[N_NODES_MAX];
__device__ int            g_partials[SCAN_NB];
__device__ int            g_row_ptr[N_NODES_MAX + 1];
__device__ int            g_cursor[N_NODES_MAX];
__device__ int            g_csr_col[N_EDGES_MAX];
__device__ float          g_csr_val[N_EDGES_MAX];

// ===========================================================================
// Kernel 0: W^T + bf16 hi/lo split.  WT[n][k] = W[k][n]
// ===========================================================================
__global__ void wt_convert_kernel(const float* __restrict__ W,
                                  __nv_bfloat16* __restrict__ wt_hi,
                                  __nv_bfloat16* __restrict__ wt_lo) {
    int k = blockIdx.x;
    int n = threadIdx.x;
    float v = W[k * DIM + n];
    __nv_bfloat16 h = __float2bfloat16_rn(v);
    __nv_bfloat16 l = __float2bfloat16_rn(v - __bfloat162float(h));
    wt_hi[n * DIM + k] = h;
    wt_lo[n * DIM + k] = l;
}

// ===========================================================================
// Kernel 1: mma.sync bf16x2-split GEMM, epilogue -> fp16 hidden
// ===========================================================================
#define SA 72
#define SB 264
#define A_HI_OFF 0
#define A_LO_OFF (128 * SA)
#define B_HI_OFF (2 * 128 * SA)
#define B_LO_OFF (2 * 128 * SA + 64 * SB)
#define GEMM_SMEM_BYTES ((2 * 128 * SA + 2 * 64 * SB) * 2)   // 104448

__device__ __forceinline__ void mma16816(float* c, const uint32_t* a, const uint32_t* b) {
    asm volatile(
        "mma.sync.aligned.m16n8k16.row.col.f32.bf16.bf16.f32 "
        "{%0,%1,%2,%3}, {%4,%5,%6,%7}, {%8,%9}, {%0,%1,%2,%3};"
        : "+f"(c[0]), "+f"(c[1]), "+f"(c[2]), "+f"(c[3])
        : "r"(a[0]), "r"(a[1]), "r"(a[2]), "r"(a[3]), "r"(b[0]), "r"(b[1]));
}

__global__ __launch_bounds__(256, 1) void gemm_mma_kernel(
        const float* __restrict__ x,
        const __nv_bfloat16* __restrict__ wt_hi,
        const __nv_bfloat16* __restrict__ wt_lo,
        __half* __restrict__ hidden, int M) {
    extern __shared__ __nv_bfloat16 sm[];

    const int tid  = threadIdx.x;
    const int warp = tid >> 5;
    const int lane = tid & 31;
    const int gid  = lane >> 2;
    const int tig  = lane & 3;
    const int wm   = warp >> 1;
    const int wn   = warp & 1;
    const int blockM = blockIdx.y * 128;
    const int blockN = blockIdx.x * 64;

#pragma unroll
    for (int t = 0; t < 8; t++) {
        int idx = tid + t * 256;
        int n = idx >> 5;
        int j = idx & 31;
        *reinterpret_cast<uint4*>(&sm[B_HI_OFF + n * SB + j * 8]) =
            *reinterpret_cast<const uint4*>(&wt_hi[(size_t)(blockN + n) * DIM + j * 8]);
        *reinterpret_cast<uint4*>(&sm[B_LO_OFF + n * SB + j * 8]) =
            *reinterpret_cast<const uint4*>(&wt_lo[(size_t)(blockN + n) * DIM + j * 8]);
    }

    float c[2][4][4];
#pragma unroll
    for (int f = 0; f < 2; f++)
#pragma unroll
        for (int g = 0; g < 4; g++)
#pragma unroll
            for (int q = 0; q < 4; q++) c[f][g][q] = 0.f;

    for (int kc = 0; kc < 4; kc++) {
        __syncthreads();
#pragma unroll
        for (int t = 0; t < 8; t++) {
            int idx = tid + t * 256;
            int row = idx >> 4;
            int c4  = idx & 15;
            float4 v = make_float4(0.f, 0.f, 0.f, 0.f);
            if (blockM + row < M)
                v = *reinterpret_cast<const float4*>(
                        &x[(size_t)(blockM + row) * DIM + kc * 64 + c4 * 4]);
            __nv_bfloat16 h0 = __float2bfloat16_rn(v.x);
            __nv_bfloat16 h1 = __float2bfloat16_rn(v.y);
            __nv_bfloat16 h2 = __float2bfloat16_rn(v.z);
            __nv_bfloat16 h3 = __float2bfloat16_rn(v.w);
            __nv_bfloat16 l0 = __float2bfloat16_rn(v.x - __bfloat162float(h0));
            __nv_bfloat16 l1 = __float2bfloat16_rn(v.y - __bfloat162float(h1));
            __nv_bfloat16 l2 = __float2bfloat16_rn(v.z - __bfloat162float(h2));
            __nv_bfloat16 l3 = __float2bfloat16_rn(v.w - __bfloat162float(h3));
            uint2 hp = make_uint2(
                ((uint32_t)__bfloat16_as_ushort(h1) << 16) | __bfloat16_as_ushort(h0),
                ((uint32_t)__bfloat16_as_ushort(h3) << 16) | __bfloat16_as_ushort(h2));
            uint2 lp = make_uint2(
                ((uint32_t)__bfloat16_as_ushort(l1) << 16) | __bfloat16_as_ushort(l0),
                ((uint32_t)__bfloat16_as_ushort(l3) << 16) | __bfloat16_as_ushort(l2));
            *reinterpret_cast<uint2*>(&sm[A_HI_OFF + row * SA + c4 * 4]) = hp;
            *reinterpret_cast<uint2*>(&sm[A_LO_OFF + row * SA + c4 * 4]) = lp;
        }
        __syncthreads();

#pragma unroll
        for (int ks = 0; ks < 4; ks++) {
            const int kb = ks * 16;
            uint32_t a_hi[2][4], a_lo[2][4], b_hi[4][2], b_lo[4][2];
#pragma unroll
            for (int f = 0; f < 2; f++) {
                int r0 = wm * 32 + f * 16;
                a_hi[f][0] = *reinterpret_cast<const uint32_t*>(&sm[A_HI_OFF + (r0 + gid)     * SA + kb + 2 * tig]);
                a_hi[f][1] = *reinterpret_cast<const uint32_t*>(&sm[A_HI_OFF + (r0 + gid + 8) * SA + kb + 2 * tig]);
                a_hi[f][2] = *reinterpret_cast<const uint32_t*>(&sm[A_HI_OFF + (r0 + gid)     * SA + kb + 2 * tig + 8]);
                a_hi[f][3] = *reinterpret_cast<const uint32_t*>(&sm[A_HI_OFF + (r0 + gid + 8) * SA + kb + 2 * tig + 8]);
                a_lo[f][0] = *reinterpret_cast<const uint32_t*>(&sm[A_LO_OFF + (r0 + gid)     * SA + kb + 2 * tig]);
                a_lo[f][1] = *reinterpret_cast<const uint32_t*>(&sm[A_LO_OFF + (r0 + gid + 8) * SA + kb + 2 * tig]);
                a_lo[f][2] = *reinterpret_cast<const uint32_t*>(&sm[A_LO_OFF + (r0 + gid)     * SA + kb + 2 * tig + 8]);
                a_lo[f][3] = *reinterpret_cast<const uint32_t*>(&sm[A_LO_OFF + (r0 + gid + 8) * SA + kb + 2 * tig + 8]);
            }
#pragma unroll
            for (int g = 0; g < 4; g++) {
                int n0 = wn * 32 + g * 8;
                int kk = kc * 64 + kb + 2 * tig;
                b_hi[g][0] = *reinterpret_cast<const uint32_t*>(&sm[B_HI_OFF + (n0 + gid) * SB + kk]);
                b_hi[g][1] = *reinterpret_cast<const uint32_t*>(&sm[B_HI_OFF + (n0 + gid) * SB + kk + 8]);
                b_lo[g][0] = *reinterpret_cast<const uint32_t*>(&sm[B_LO_OFF + (n0 + gid) * SB + kk]);
                b_lo[g][1] = *reinterpret_cast<const uint32_t*>(&sm[B_LO_OFF + (n0 + gid) * SB + kk + 8]);
            }
#pragma unroll
            for (int f = 0; f < 2; f++)
#pragma unroll
                for (int g = 0; g < 4; g++) {
                    mma16816(c[f][g], a_hi[f], b_hi[g]);
                    mma16816(c[f][g], a_hi[f], b_lo[g]);
                    mma16816(c[f][g], a_lo[f], b_hi[g]);
                }
        }
    }

    // epilogue -> fp16
#pragma unroll
    for (int f = 0; f < 2; f++) {
#pragma unroll
        for (int g = 0; g < 4; g++) {
            int row = blockM + wm * 32 + f * 16 + gid;
            int col = blockN + wn * 32 + g * 8 + 2 * tig;
            if (row < M)
                *reinterpret_cast<__half2*>(&hidden[(size_t)row * DIM + col]) =
                    __floats2half2_rn(c[f][g][0], c[f][g][1]);
            if (row + 8 < M)
                *reinterpret_cast<__half2*>(&hidden[(size_t)(row + 8) * DIM + col]) =
                    __floats2half2_rn(c[f][g][2], c[f][g][3]);
        }
    }
}

// ===========================================================================
// CSR build: histogram + 3-phase multi-block scan + scatter
// ===========================================================================
__global__ void hist_kernel(const int* __restrict__ rows, int* __restrict__ counts, int E) {
    int i = blockIdx.x * blockDim.x + threadIdx.x;
    if (i < E) atomicAdd(&counts[rows[i]], 1);
}

__device__ __forceinline__ int block_scan_inclusive(int v, int tid) {
    __shared__ int wsum[8];
    const int lane = tid & 31, wid = tid >> 5;
#pragma unroll
    for (int off = 1; off < 32; off <<= 1) {
        int n = __shfl_up_sync(0xffffffffu, v, off);
        if (lane >= off) v += n;
    }
    if (lane == 31) wsum[wid] = v;
    __syncthreads();
    if (wid == 0) {
        int s = (lane < 8) ? wsum[lane] : 0;
#pragma unroll
        for (int off = 1; off < 8; off <<= 1) {
            int n = __shfl_up_sync(0xffffffffu, s, off);
            if (lane >= off) s += n;
        }
        if (lane < 8) wsum[lane] = s;
    }
    __syncthreads();
    if (wid > 0) v += wsum[wid - 1];
    return v;
}

// phase 1: per-block sums of counts
__global__ __launch_bounds__(256) void scan_partial_kernel(const int* __restrict__ counts,
                                                           int* __restrict__ partials, int M) {
    __shared__ int wsum[8];
    int i = blockIdx.x * 256 + threadIdx.x;
    int v = (i < M) ? counts[i] : 0;
    const int lane = threadIdx.x & 31, wid = threadIdx.x >> 5;
#pragma unroll
    for (int off = 16; off > 0; off >>= 1) v += __shfl_down_sync(0xffffffffu, v, off);
    if (lane == 0) wsum[wid] = v;
    __syncthreads();
    if (threadIdx.x == 0) {
        int s = 0;
#pragma unroll
        for (int k = 0; k < 8; k++) s += wsum[k];
        partials[blockIdx.x] = s;
    }
}

// phase 2: single block converts partials -> exclusive offsets
__global__ __launch_bounds__(256) void scan_offsets_kernel(int* __restrict__ partials, int NB) {
    int t = threadIdx.x;
    int v = (t < NB) ? partials[t] : 0;
    int incl = block_scan_inclusive(v, t);
    if (t < NB) partials[t] = incl - v;
}

// phase 3: per-block exclusive scan + offset -> row_ptr, cursor
__global__ __launch_bounds__(256) void scan_final_kernel(const int* __restrict__ counts,
                                                         const int* __restrict__ partials,
                                                         int* __restrict__ row_ptr,
                                                         int* __restrict__ cursor,
                                                         int M, int E) {
    int i = blockIdx.x * 256 + threadIdx.x;
    int v = (i < M) ? counts[i] : 0;
    int incl = block_scan_inclusive(v, threadIdx.x);
    int excl = incl - v + partials[blockIdx.x];
    if (i < M) {
        row_ptr[i] = excl;
        cursor[i]  = excl;
    }
    if (i == 0) row_ptr[M] = E;
}

__global__ void scatter_kernel(const int* __restrict__ rows,
                               const int* __restrict__ cols,
                               const float* __restrict__ vals,
                               int*   __restrict__ cursor,
                               int*   __restrict__ csr_col,
                               float* __restrict__ csr_val,
                               int E) {
    int i = blockIdx.x * blockDim.x + threadIdx.x;
    if (i < E) {
        int r   = rows[i];
        int pos = atomicAdd(&cursor[r], 1);
        csr_col[pos] = cols[i];
        csr_val[pos] = vals[i];
    }
}

// ===========================================================================
// SpMM: warp per destination row, fp16 hidden. Lane owns 8 dims = one 16B
// gather per edge. 2-edge unroll -> 2 outstanding 16B loads per lane.
// ===========================================================================
__device__ __forceinline__ void fma8_half(float* acc, uint4 r, float v) {
    float2 f0 = __half22float2(*reinterpret_cast<__half2*>(&r.x));
    float2 f1 = __half22float2(*reinterpret_cast<__half2*>(&r.y));
    float2 f2 = __half22float2(*reinterpret_cast<__half2*>(&r.z));
    float2 f3 = __half22float2(*reinterpret_cast<__half2*>(&r.w));
    acc[0] = fmaf(v, f0.x, acc[0]); acc[1] = fmaf(v, f0.y, acc[1]);
    acc[2] = fmaf(v, f1.x, acc[2]); acc[3] = fmaf(v, f1.y, acc[3]);
    acc[4] = fmaf(v, f2.x, acc[4]); acc[5] = fmaf(v, f2.y, acc[5]);
    acc[6] = fmaf(v, f3.x, acc[6]); acc[7] = fmaf(v, f3.y, acc[7]);
}

__global__ __launch_bounds__(256) void spmm_warp_kernel(const int*   __restrict__ row_ptr,
                                                        const int*   __restrict__ csr_col,
                                                        const float* __restrict__ csr_val,
                                                        const __half* __restrict__ hidden,
                                                        const float* __restrict__ b,
                                                        float*       __restrict__ out,
                                                        int M) {
    const int w    = (blockIdx.x * blockDim.x + threadIdx.x) >> 5;
    const int lane = threadIdx.x & 31;
    if (w >= M) return;

    const int s = row_ptr[w];
    const int e = row_ptr[w + 1];

    float acc[8];
#pragma unroll
    for (int q = 0; q < 8; q++) acc[q] = 0.f;

    for (int base = s; base < e; base += 32) {
        int   i = base + lane;
        int   cc = 0;
        float vv = 0.f;
        if (i < e) { cc = csr_col[i]; vv = csr_val[i]; }
        int cnt = min(32, e - base);

        int j = 0;
        for (; j + 1 < cnt; j += 2) {
            int   c0 = __shfl_sync(0xffffffffu, cc, j);
            float v0 = __shfl_sync(0xffffffffu, vv, j);
            int   c1 = __shfl_sync(0xffffffffu, cc, j + 1);
            float v1 = __shfl_sync(0xffffffffu, vv, j + 1);
            uint4 r0 = reinterpret_cast<const uint4*>(hidden + (size_t)c0 * DIM)[lane];
            uint4 r1 = reinterpret_cast<const uint4*>(hidden + (size_t)c1 * DIM)[lane];
            fma8_half(acc, r0, v0);
            fma8_half(acc, r1, v1);
        }
        if (j < cnt) {
            int   c0 = __shfl_sync(0xffffffffu, cc, j);
            float v0 = __shfl_sync(0xffffffffu, vv, j);
            uint4 r0 = reinterpret_cast<const uint4*>(hidden + (size_t)c0 * DIM)[lane];
            fma8_half(acc, r0, v0);
        }
    }

    const float4* b4 = reinterpret_cast<const float4*>(b + lane * 8);
    float4 bb0 = b4[0], bb1 = b4[1];
    float4* o = reinterpret_cast<float4*>(out + (size_t)w * DIM + lane * 8);
    o[0] = make_float4(acc[0] + bb0.x, acc[1] + bb0.y, acc[2] + bb0.z, acc[3] + bb0.w);
    o[1] = make_float4(acc[4] + bb1.x, acc[5] + bb1.y, acc[6] + bb1.z, acc[7] + bb1.w);
}

// ===========================================================================
// Launch
// ===========================================================================
extern "C" void kernel_launch(void* const* d_in, const int* in_sizes, int n_in,
                              void* d_out, int out_size) {
    const float* x        = (const float*)d_in[0];
    const int*   adj_rows = (const int*)  d_in[1];
    const int*   adj_cols = (const int*)  d_in[2];
    const float* adj_vals = (const float*)d_in[3];
    const float* W        = (const float*)d_in[4];
    const float* b        = (const float*)d_in[5];
    float*       out      = (float*)d_out;

    const int M = in_sizes[0] / DIM;   // 50000
    const int E = in_sizes[1];         // 800000

    __half *hidden;
    float *csr_val;
    __nv_bfloat16 *wt_hi, *wt_lo;
    int *counts, *partials, *row_ptr, *cursor, *csr_col;
    cudaGetSymbolAddress((void**)&hidden,   g_hidden_h);
    cudaGetSymbolAddress((void**)&wt_hi,    g_WT_hi);
    cudaGetSymbolAddress((void**)&wt_lo,    g_WT_lo);
    cudaGetSymbolAddress((void**)&counts,   g_counts);
    cudaGetSymbolAddress((void**)&partials, g_partials);
    cudaGetSymbolAddress((void**)&row_ptr,  g_row_ptr);
    cudaGetSymbolAddress((void**)&cursor,   g_cursor);
    cudaGetSymbolAddress((void**)&csr_col,  g_csr_col);
    cudaGetSymbolAddress((void**)&csr_val,  g_csr_val);

    const int NB = (M + 255) / 256;

    // 0) split-transpose W
    wt_convert_kernel<<<DIM, DIM>>>(W, wt_hi, wt_lo);

    // 1) hidden = x @ W  (mma.sync bf16x2 -> fp16)
    static bool attr_set = false;
    if (!attr_set) {
        cudaFuncSetAttribute(gemm_mma_kernel,
                             cudaFuncAttributeMaxDynamicSharedMemorySize, GEMM_SMEM_BYTES);
        attr_set = true;
    }
    dim3 gemmGrid(DIM / 64, (M + 127) / 128);
    gemm_mma_kernel<<<gemmGrid, 256, GEMM_SMEM_BYTES>>>(x, wt_hi, wt_lo, hidden, M);

    // 2) CSR build
    cudaMemsetAsync(counts, 0, (size_t)M * sizeof(int));
    hist_kernel<<<(E + 255) / 256, 256>>>(adj_rows, counts, E);
    scan_partial_kernel<<<NB, 256>>>(counts, partials, M);
    scan_offsets_kernel<<<1, 256>>>(partials, NB);
    scan_final_kernel<<<NB, 256>>>(counts, partials, row_ptr, cursor, M, E);
    scatter_kernel<<<(E + 255) / 256, 256>>>(adj_rows, adj_cols, adj_vals,
                                             cursor, csr_col, csr_val, E);

    // 3) out = adj @ hidden + b  (warp per row, fp16 gathers)
    spmm_warp_kernel<<<(M * 32 + 255) / 256, 256>>>(row_ptr, csr_col, csr_val,
                                                    hidden, b, out, M);
}

// round 6
// speedup vs baseline: 6.4866x; 1.0521x over previous
#include <cuda_runtime.h>
#include <cuda_bf16.h>
#include <cuda_fp16.h>
#include <cstdint>

#define DIM 256
#define N_NODES_MAX 50000
#define N_EDGES_MAX 800000
#define SCAN_NB ((N_NODES_MAX + 255) / 256)   // 196

// ----- scratch (__device__ globals; no cudaMalloc allowed) -----
__device__ __half         g_hidden_h[N_NODES_MAX * DIM]; // x @ W (fp16)
__device__ __nv_bfloat16  g_WT_hi[DIM * DIM];            // W^T hi split (WT[n][k])
__device__ __nv_bfloat16  g_WT_lo[DIM * DIM];            // W^T lo split
__device__ int            g_counts[N_NODES_MAX];
__device__ int            g_partials[SCAN_NB];
__device__ int            g_row_ptr[N_NODES_MAX + 1];
__device__ int            g_cursor[N_NODES_MAX];
__device__ int            g_csr_col[N_EDGES_MAX];
__device__ float          g_csr_val[N_EDGES_MAX];

// ===========================================================================
// Kernel 0: W^T + bf16 hi/lo split.  WT[n][k] = W[k][n]
// ===========================================================================
__global__ void wt_convert_kernel(const float* __restrict__ W,
                                  __nv_bfloat16* __restrict__ wt_hi,
                                  __nv_bfloat16* __restrict__ wt_lo) {
    int k = blockIdx.x;
    int n = threadIdx.x;
    float v = W[k * DIM + n];
    __nv_bfloat16 h = __float2bfloat16_rn(v);
    __nv_bfloat16 l = __float2bfloat16_rn(v - __bfloat162float(h));
    wt_hi[n * DIM + k] = h;
    wt_lo[n * DIM + k] = l;
}

// ===========================================================================
// Kernel 1: mma.sync bf16x2-split GEMM, epilogue -> fp16 hidden
// ===========================================================================
#define SA 72
#define SB 264
#define A_HI_OFF 0
#define A_LO_OFF (128 * SA)
#define B_HI_OFF (2 * 128 * SA)
#define B_LO_OFF (2 * 128 * SA + 64 * SB)
#define GEMM_SMEM_BYTES ((2 * 128 * SA + 2 * 64 * SB) * 2)   // 104448

__device__ __forceinline__ void mma16816(float* c, const uint32_t* a, const uint32_t* b) {
    asm volatile(
        "mma.sync.aligned.m16n8k16.row.col.f32.bf16.bf16.f32 "
        "{%0,%1,%2,%3}, {%4,%5,%6,%7}, {%8,%9}, {%0,%1,%2,%3};"
        : "+f"(c[0]), "+f"(c[1]), "+f"(c[2]), "+f"(c[3])
        : "r"(a[0]), "r"(a[1]), "r"(a[2]), "r"(a[3]), "r"(b[0]), "r"(b[1]));
}

__global__ __launch_bounds__(256, 1) void gemm_mma_kernel(
        const float* __restrict__ x,
        const __nv_bfloat16* __restrict__ wt_hi,
        const __nv_bfloat16* __restrict__ wt_lo,
        __half* __restrict__ hidden, int M) {
    extern __shared__ __nv_bfloat16 sm[];

    const int tid  = threadIdx.x;
    const int warp = tid >> 5;
    const int lane = tid & 31;
    const int gid  = lane >> 2;
    const int tig  = lane & 3;
    const int wm   = warp >> 1;
    const int wn   = warp & 1;
    const int blockM = blockIdx.y * 128;
    const int blockN = blockIdx.x * 64;

#pragma unroll
    for (int t = 0; t < 8; t++) {
        int idx = tid + t * 256;
        int n = idx >> 5;
        int j = idx & 31;
        *reinterpret_cast<uint4*>(&sm[B_HI_OFF + n * SB + j * 8]) =
            *reinterpret_cast<const uint4*>(&wt_hi[(size_t)(blockN + n) * DIM + j * 8]);
        *reinterpret_cast<uint4*>(&sm[B_LO_OFF + n * SB + j * 8]) =
            *reinterpret_cast<const uint4*>(&wt_lo[(size_t)(blockN + n) * DIM + j * 8]);
    }

    float c[2][4][4];
#pragma unroll
    for (int f = 0; f < 2; f++)
#pragma unroll
        for (int g = 0; g < 4; g++)
#pragma unroll
            for (int q = 0; q < 4; q++) c[f][g][q] = 0.f;

    for (int kc = 0; kc < 4; kc++) {
        __syncthreads();
#pragma unroll
        for (int t = 0; t < 8; t++) {
            int idx = tid + t * 256;
            int row = idx >> 4;
            int c4  = idx & 15;
            float4 v = make_float4(0.f, 0.f, 0.f, 0.f);
            if (blockM + row < M)
                v = *reinterpret_cast<const float4*>(
                        &x[(size_t)(blockM + row) * DIM + kc * 64 + c4 * 4]);
            __nv_bfloat16 h0 = __float2bfloat16_rn(v.x);
            __nv_bfloat16 h1 = __float2bfloat16_rn(v.y);
            __nv_bfloat16 h2 = __float2bfloat16_rn(v.z);
            __nv_bfloat16 h3 = __float2bfloat16_rn(v.w);
            __nv_bfloat16 l0 = __float2bfloat16_rn(v.x - __bfloat162float(h0));
            __nv_bfloat16 l1 = __float2bfloat16_rn(v.y - __bfloat162float(h1));
            __nv_bfloat16 l2 = __float2bfloat16_rn(v.z - __bfloat162float(h2));
            __nv_bfloat16 l3 = __float2bfloat16_rn(v.w - __bfloat162float(h3));
            uint2 hp = make_uint2(
                ((uint32_t)__bfloat16_as_ushort(h1) << 16) | __bfloat16_as_ushort(h0),
                ((uint32_t)__bfloat16_as_ushort(h3) << 16) | __bfloat16_as_ushort(h2));
            uint2 lp = make_uint2(
                ((uint32_t)__bfloat16_as_ushort(l1) << 16) | __bfloat16_as_ushort(l0),
                ((uint32_t)__bfloat16_as_ushort(l3) << 16) | __bfloat16_as_ushort(l2));
            *reinterpret_cast<uint2*>(&sm[A_HI_OFF + row * SA + c4 * 4]) = hp;
            *reinterpret_cast<uint2*>(&sm[A_LO_OFF + row * SA + c4 * 4]) = lp;
        }
        __syncthreads();

#pragma unroll
        for (int ks = 0; ks < 4; ks++) {
            const int kb = ks * 16;
            uint32_t a_hi[2][4], a_lo[2][4], b_hi[4][2], b_lo[4][2];
#pragma unroll
            for (int f = 0; f < 2; f++) {
                int r0 = wm * 32 + f * 16;
                a_hi[f][0] = *reinterpret_cast<const uint32_t*>(&sm[A_HI_OFF + (r0 + gid)     * SA + kb + 2 * tig]);
                a_hi[f][1] = *reinterpret_cast<const uint32_t*>(&sm[A_HI_OFF + (r0 + gid + 8) * SA + kb + 2 * tig]);
                a_hi[f][2] = *reinterpret_cast<const uint32_t*>(&sm[A_HI_OFF + (r0 + gid)     * SA + kb + 2 * tig + 8]);
                a_hi[f][3] = *reinterpret_cast<const uint32_t*>(&sm[A_HI_OFF + (r0 + gid + 8) * SA + kb + 2 * tig + 8]);
                a_lo[f][0] = *reinterpret_cast<const uint32_t*>(&sm[A_LO_OFF + (r0 + gid)     * SA + kb + 2 * tig]);
                a_lo[f][1] = *reinterpret_cast<const uint32_t*>(&sm[A_LO_OFF + (r0 + gid + 8) * SA + kb + 2 * tig]);
                a_lo[f][2] = *reinterpret_cast<const uint32_t*>(&sm[A_LO_OFF + (r0 + gid)     * SA + kb + 2 * tig + 8]);
                a_lo[f][3] = *reinterpret_cast<const uint32_t*>(&sm[A_LO_OFF + (r0 + gid + 8) * SA + kb + 2 * tig + 8]);
            }
#pragma unroll
            for (int g = 0; g < 4; g++) {
                int n0 = wn * 32 + g * 8;
                int kk = kc * 64 + kb + 2 * tig;
                b_hi[g][0] = *reinterpret_cast<const uint32_t*>(&sm[B_HI_OFF + (n0 + gid) * SB + kk]);
                b_hi[g][1] = *reinterpret_cast<const uint32_t*>(&sm[B_HI_OFF + (n0 + gid) * SB + kk + 8]);
                b_lo[g][0] = *reinterpret_cast<const uint32_t*>(&sm[B_LO_OFF + (n0 + gid) * SB + kk]);
                b_lo[g][1] = *reinterpret_cast<const uint32_t*>(&sm[B_LO_OFF + (n0 + gid) * SB + kk + 8]);
            }
#pragma unroll
            for (int f = 0; f < 2; f++)
#pragma unroll
                for (int g = 0; g < 4; g++) {
                    mma16816(c[f][g], a_hi[f], b_hi[g]);
                    mma16816(c[f][g], a_hi[f], b_lo[g]);
                    mma16816(c[f][g], a_lo[f], b_hi[g]);
                }
        }
    }

    // epilogue -> fp16
#pragma unroll
    for (int f = 0; f < 2; f++) {
#pragma unroll
        for (int g = 0; g < 4; g++) {
            int row = blockM + wm * 32 + f * 16 + gid;
            int col = blockN + wn * 32 + g * 8 + 2 * tig;
            if (row < M)
                *reinterpret_cast<__half2*>(&hidden[(size_t)row * DIM + col]) =
                    __floats2half2_rn(c[f][g][0], c[f][g][1]);
            if (row + 8 < M)
                *reinterpret_cast<__half2*>(&hidden[(size_t)(row + 8) * DIM + col]) =
                    __floats2half2_rn(c[f][g][2], c[f][g][3]);
        }
    }
}

// ===========================================================================
// CSR build: histogram + 3-phase multi-block scan + scatter
// ===========================================================================
__global__ void hist_kernel(const int* __restrict__ rows, int* __restrict__ counts, int E) {
    int i = blockIdx.x * blockDim.x + threadIdx.x;
    if (i < E) atomicAdd(&counts[rows[i]], 1);
}

__device__ __forceinline__ int block_scan_inclusive(int v, int tid) {
    __shared__ int wsum[8];
    const int lane = tid & 31, wid = tid >> 5;
#pragma unroll
    for (int off = 1; off < 32; off <<= 1) {
        int n = __shfl_up_sync(0xffffffffu, v, off);
        if (lane >= off) v += n;
    }
    if (lane == 31) wsum[wid] = v;
    __syncthreads();
    if (wid == 0) {
        int s = (lane < 8) ? wsum[lane] : 0;
#pragma unroll
        for (int off = 1; off < 8; off <<= 1) {
            int n = __shfl_up_sync(0xffffffffu, s, off);
            if (lane >= off) s += n;
        }
        if (lane < 8) wsum[lane] = s;
    }
    __syncthreads();
    if (wid > 0) v += wsum[wid - 1];
    return v;
}

__global__ __launch_bounds__(256) void scan_partial_kernel(const int* __restrict__ counts,
                                                           int* __restrict__ partials, int M) {
    __shared__ int wsum[8];
    int i = blockIdx.x * 256 + threadIdx.x;
    int v = (i < M) ? counts[i] : 0;
    const int lane = threadIdx.x & 31, wid = threadIdx.x >> 5;
#pragma unroll
    for (int off = 16; off > 0; off >>= 1) v += __shfl_down_sync(0xffffffffu, v, off);
    if (lane == 0) wsum[wid] = v;
    __syncthreads();
    if (threadIdx.x == 0) {
        int s = 0;
#pragma unroll
        for (int k = 0; k < 8; k++) s += wsum[k];
        partials[blockIdx.x] = s;
    }
}

__global__ __launch_bounds__(256) void scan_offsets_kernel(int* __restrict__ partials, int NB) {
    int t = threadIdx.x;
    int v = (t < NB) ? partials[t] : 0;
    int incl = block_scan_inclusive(v, t);
    if (t < NB) partials[t] = incl - v;
}

__global__ __launch_bounds__(256) void scan_final_kernel(const int* __restrict__ counts,
                                                         const int* __restrict__ partials,
                                                         int* __restrict__ row_ptr,
                                                         int* __restrict__ cursor,
                                                         int M, int E) {
    int i = blockIdx.x * 256 + threadIdx.x;
    int v = (i < M) ? counts[i] : 0;
    int incl = block_scan_inclusive(v, threadIdx.x);
    int excl = incl - v + partials[blockIdx.x];
    if (i < M) {
        row_ptr[i] = excl;
        cursor[i]  = excl;
    }
    if (i == 0) row_ptr[M] = E;
}

__global__ void scatter_kernel(const int* __restrict__ rows,
                               const int* __restrict__ cols,
                               const float* __restrict__ vals,
                               int*   __restrict__ cursor,
                               int*   __restrict__ csr_col,
                               float* __restrict__ csr_val,
                               int E) {
    int i = blockIdx.x * blockDim.x + threadIdx.x;
    if (i < E) {
        int r   = rows[i];
        int pos = atomicAdd(&cursor[r], 1);
        csr_col[pos] = cols[i];
        csr_val[pos] = vals[i];
    }
}

// ===========================================================================
// SpMM: warp per destination row, fp16 hidden, 4-edge unroll (MLP=4/lane).
// ===========================================================================
__device__ __forceinline__ void fma8_half(float* acc, uint4 r, float v) {
    float2 f0 = __half22float2(*reinterpret_cast<__half2*>(&r.x));
    float2 f1 = __half22float2(*reinterpret_cast<__half2*>(&r.y));
    float2 f2 = __half22float2(*reinterpret_cast<__half2*>(&r.z));
    float2 f3 = __half22float2(*reinterpret_cast<__half2*>(&r.w));
    acc[0] = fmaf(v, f0.x, acc[0]); acc[1] = fmaf(v, f0.y, acc[1]);
    acc[2] = fmaf(v, f1.x, acc[2]); acc[3] = fmaf(v, f1.y, acc[3]);
    acc[4] = fmaf(v, f2.x, acc[4]); acc[5] = fmaf(v, f2.y, acc[5]);
    acc[6] = fmaf(v, f3.x, acc[6]); acc[7] = fmaf(v, f3.y, acc[7]);
}

__global__ __launch_bounds__(256) void spmm_warp_kernel(const int*   __restrict__ row_ptr,
                                                        const int*   __restrict__ csr_col,
                                                        const float* __restrict__ csr_val,
                                                        const __half* __restrict__ hidden,
                                                        const float* __restrict__ b,
                                                        float*       __restrict__ out,
                                                        int M) {
    const int w    = (blockIdx.x * blockDim.x + threadIdx.x) >> 5;
    const int lane = threadIdx.x & 31;
    if (w >= M) return;

    const int s = row_ptr[w];
    const int e = row_ptr[w + 1];

    float acc[8];
#pragma unroll
    for (int q = 0; q < 8; q++) acc[q] = 0.f;

    for (int base = s; base < e; base += 32) {
        int   i = base + lane;
        int   cc = 0;
        float vv = 0.f;
        if (i < e) { cc = csr_col[i]; vv = csr_val[i]; }
        int cnt = min(32, e - base);

        int j = 0;
        for (; j + 3 < cnt; j += 4) {
            int   c0 = __shfl_sync(0xffffffffu, cc, j);
            int   c1 = __shfl_sync(0xffffffffu, cc, j + 1);
            int   c2 = __shfl_sync(0xffffffffu, cc, j + 2);
            int   c3 = __shfl_sync(0xffffffffu, cc, j + 3);
            float v0 = __shfl_sync(0xffffffffu, vv, j);
            float v1 = __shfl_sync(0xffffffffu, vv, j + 1);
            float v2 = __shfl_sync(0xffffffffu, vv, j + 2);
            float v3 = __shfl_sync(0xffffffffu, vv, j + 3);
            uint4 r0 = reinterpret_cast<const uint4*>(hidden + (size_t)c0 * DIM)[lane];
            uint4 r1 = reinterpret_cast<const uint4*>(hidden + (size_t)c1 * DIM)[lane];
            uint4 r2 = reinterpret_cast<const uint4*>(hidden + (size_t)c2 * DIM)[lane];
            uint4 r3 = reinterpret_cast<const uint4*>(hidden + (size_t)c3 * DIM)[lane];
            fma8_half(acc, r0, v0);
            fma8_half(acc, r1, v1);
            fma8_half(acc, r2, v2);
            fma8_half(acc, r3, v3);
        }
        for (; j < cnt; j++) {
            int   c0 = __shfl_sync(0xffffffffu, cc, j);
            float v0 = __shfl_sync(0xffffffffu, vv, j);
            uint4 r0 = reinterpret_cast<const uint4*>(hidden + (size_t)c0 * DIM)[lane];
            fma8_half(acc, r0, v0);
        }
    }

    const float4* b4 = reinterpret_cast<const float4*>(b + lane * 8);
    float4 bb0 = b4[0], bb1 = b4[1];
    float4* o = reinterpret_cast<float4*>(out + (size_t)w * DIM + lane * 8);
    o[0] = make_float4(acc[0] + bb0.x, acc[1] + bb0.y, acc[2] + bb0.z, acc[3] + bb0.w);
    o[1] = make_float4(acc[4] + bb1.x, acc[5] + bb1.y, acc[6] + bb1.z, acc[7] + bb1.w);
}

// ===========================================================================
// Launch — GEMM branch and CSR branch fork/join so they run concurrently
// (both in live execution and as parallel branches in the captured graph).
// Streams/events are created on the first (uncaptured) correctness call.
// ===========================================================================
extern "C" void kernel_launch(void* const* d_in, const int* in_sizes, int n_in,
                              void* d_out, int out_size) {
    const float* x        = (const float*)d_in[0];
    const int*   adj_rows = (const int*)  d_in[1];
    const int*   adj_cols = (const int*)  d_in[2];
    const float* adj_vals = (const float*)d_in[3];
    const float* W        = (const float*)d_in[4];
    const float* b        = (const float*)d_in[5];
    float*       out      = (float*)d_out;

    const int M = in_sizes[0] / DIM;   // 50000
    const int E = in_sizes[1];         // 800000

    __half *hidden;
    float *csr_val;
    __nv_bfloat16 *wt_hi, *wt_lo;
    int *counts, *partials, *row_ptr, *cursor, *csr_col;
    cudaGetSymbolAddress((void**)&hidden,   g_hidden_h);
    cudaGetSymbolAddress((void**)&wt_hi,    g_WT_hi);
    cudaGetSymbolAddress((void**)&wt_lo,    g_WT_lo);
    cudaGetSymbolAddress((void**)&counts,   g_counts);
    cudaGetSymbolAddress((void**)&partials, g_partials);
    cudaGetSymbolAddress((void**)&row_ptr,  g_row_ptr);
    cudaGetSymbolAddress((void**)&cursor,   g_cursor);
    cudaGetSymbolAddress((void**)&csr_col,  g_csr_col);
    cudaGetSymbolAddress((void**)&csr_val,  g_csr_val);

    const int NB = (M + 255) / 256;

    static cudaStream_t s_csr = nullptr;
    static cudaEvent_t  ev_fork = nullptr, ev_join = nullptr;
    if (s_csr == nullptr) {
        cudaStreamCreateWithFlags(&s_csr, cudaStreamNonBlocking);
        cudaEventCreateWithFlags(&ev_fork, cudaEventDisableTiming);
        cudaEventCreateWithFlags(&ev_join, cudaEventDisableTiming);
        cudaFuncSetAttribute(gemm_mma_kernel,
                             cudaFuncAttributeMaxDynamicSharedMemorySize, GEMM_SMEM_BYTES);
    }

    // ---- fork: CSR branch on s_csr ----
    cudaEventRecord(ev_fork, 0);
    cudaStreamWaitEvent(s_csr, ev_fork, 0);

    cudaMemsetAsync(counts, 0, (size_t)M * sizeof(int), s_csr);
    hist_kernel<<<(E + 255) / 256, 256, 0, s_csr>>>(adj_rows, counts, E);
    scan_partial_kernel<<<NB, 256, 0, s_csr>>>(counts, partials, M);
    scan_offsets_kernel<<<1, 256, 0, s_csr>>>(partials, NB);
    scan_final_kernel<<<NB, 256, 0, s_csr>>>(counts, partials, row_ptr, cursor, M, E);
    scatter_kernel<<<(E + 255) / 256, 256, 0, s_csr>>>(adj_rows, adj_cols, adj_vals,
                                                       cursor, csr_col, csr_val, E);
    cudaEventRecord(ev_join, s_csr);

    // ---- GEMM branch on the capture (default) stream ----
    wt_convert_kernel<<<DIM, DIM>>>(W, wt_hi, wt_lo);
    dim3 gemmGrid(DIM / 64, (M + 127) / 128);
    gemm_mma_kernel<<<gemmGrid, 256, GEMM_SMEM_BYTES>>>(x, wt_hi, wt_lo, hidden, M);

    // ---- join, then SpMM ----
    cudaStreamWaitEvent(0, ev_join, 0);
    spmm_warp_kernel<<<(M * 32 + 255) / 256, 256>>>(row_ptr, csr_col, csr_val,
                                                    hidden, b, out, M);
}

// round 7
// speedup vs baseline: 10.3709x; 1.5988x over previous
#include <cuda_runtime.h>
#include <cuda_bf16.h>
#include <cuda_fp16.h>
#include <cstdint>

#define DIM 256
#define N_NODES_MAX 50000
#define N_EDGES_MAX 800000
#define SCAN_NB ((N_NODES_MAX + 255) / 256)   // 196

// ----- scratch (__device__ globals; no cudaMalloc allowed) -----
__device__ __half         g_hidden_h[N_NODES_MAX * DIM]; // x @ W (fp16)
__device__ __half         g_WT[DIM * DIM];               // W^T fp16 (WT[n][k])
__device__ int            g_counts[N_NODES_MAX];
__device__ int            g_partials[SCAN_NB];
__device__ int            g_row_ptr[N_NODES_MAX + 1];
__device__ int            g_cursor[N_NODES_MAX];
__device__ int2           g_csr_pack[N_EDGES_MAX];       // (col, val-bits)

// ===========================================================================
// Kernel 0: W^T fp16.  WT[n][k] = W[k][n]
// ===========================================================================
__global__ void wt_convert_kernel(const float* __restrict__ W,
                                  __half* __restrict__ wt) {
    int k = blockIdx.x;
    int n = threadIdx.x;
    wt[n * DIM + k] = __float2half_rn(W[k * DIM + n]);
}

// ===========================================================================
// Kernel 1: mma.sync fp16 GEMM  hidden[M,256] = x[M,256] @ W[256,256]
// Block 256 thr = 8 warps (4Mx2N), tile 128x64, warp tile 32x32, fp32 accum.
// ===========================================================================
#define SA 72     // A smem row stride (64 + 8 pad) in halves
#define SB 264    // B smem row stride (256 + 8 pad) in halves
#define A_OFF 0
#define B_OFF (128 * SA)
#define GEMM_SMEM_BYTES ((128 * SA + 64 * SB) * 2)   // 52224

__device__ __forceinline__ void mma16816(float* c, const uint32_t* a, const uint32_t* b) {
    asm volatile(
        "mma.sync.aligned.m16n8k16.row.col.f32.f16.f16.f32 "
        "{%0,%1,%2,%3}, {%4,%5,%6,%7}, {%8,%9}, {%0,%1,%2,%3};"
        : "+f"(c[0]), "+f"(c[1]), "+f"(c[2]), "+f"(c[3])
        : "r"(a[0]), "r"(a[1]), "r"(a[2]), "r"(a[3]), "r"(b[0]), "r"(b[1]));
}

__global__ __launch_bounds__(256, 2) void gemm_mma_kernel(
        const float* __restrict__ x,
        const __half* __restrict__ wt,
        __half* __restrict__ hidden, int M) {
    extern __shared__ __half sm[];

    const int tid  = threadIdx.x;
    const int warp = tid >> 5;
    const int lane = tid & 31;
    const int gid  = lane >> 2;
    const int tig  = lane & 3;
    const int wm   = warp >> 1;
    const int wn   = warp & 1;
    const int blockM = blockIdx.y * 128;
    const int blockN = blockIdx.x * 64;

    // ---- load B tile (full K): 64 rows x 256 k ----
#pragma unroll
    for (int t = 0; t < 8; t++) {
        int idx = tid + t * 256;          // 0..2047
        int n = idx >> 5;
        int j = idx & 31;
        *reinterpret_cast<uint4*>(&sm[B_OFF + n * SB + j * 8]) =
            *reinterpret_cast<const uint4*>(&wt[(size_t)(blockN + n) * DIM + j * 8]);
    }

    float c[2][4][4];
#pragma unroll
    for (int f = 0; f < 2; f++)
#pragma unroll
        for (int g = 0; g < 4; g++)
#pragma unroll
            for (int q = 0; q < 4; q++) c[f][g][q] = 0.f;

    for (int kc = 0; kc < 4; kc++) {
        __syncthreads();
        // ---- stage A chunk: x[blockM..+128, kc*64..+64] fp32 -> fp16 ----
#pragma unroll
        for (int t = 0; t < 8; t++) {
            int idx = tid + t * 256;      // 0..2047 float4 slots
            int row = idx >> 4;
            int c4  = idx & 15;
            float4 v = make_float4(0.f, 0.f, 0.f, 0.f);
            if (blockM + row < M)
                v = *reinterpret_cast<const float4*>(
                        &x[(size_t)(blockM + row) * DIM + kc * 64 + c4 * 4]);
            __half2 p0 = __floats2half2_rn(v.x, v.y);
            __half2 p1 = __floats2half2_rn(v.z, v.w);
            *reinterpret_cast<uint2*>(&sm[A_OFF + row * SA + c4 * 4]) =
                make_uint2(*reinterpret_cast<uint32_t*>(&p0),
                           *reinterpret_cast<uint32_t*>(&p1));
        }
        __syncthreads();

#pragma unroll
        for (int ks = 0; ks < 4; ks++) {
            const int kb = ks * 16;
            uint32_t a[2][4], bb[4][2];
#pragma unroll
            for (int f = 0; f < 2; f++) {
                int r0 = wm * 32 + f * 16;
                a[f][0] = *reinterpret_cast<const uint32_t*>(&sm[A_OFF + (r0 + gid)     * SA + kb + 2 * tig]);
                a[f][1] = *reinterpret_cast<const uint32_t*>(&sm[A_OFF + (r0 + gid + 8) * SA + kb + 2 * tig]);
                a[f][2] = *reinterpret_cast<const uint32_t*>(&sm[A_OFF + (r0 + gid)     * SA + kb + 2 * tig + 8]);
                a[f][3] = *reinterpret_cast<const uint32_t*>(&sm[A_OFF + (r0 + gid + 8) * SA + kb + 2 * tig + 8]);
            }
#pragma unroll
            for (int g = 0; g < 4; g++) {
                int n0 = wn * 32 + g * 8;
                int kk = kc * 64 + kb + 2 * tig;
                bb[g][0] = *reinterpret_cast<const uint32_t*>(&sm[B_OFF + (n0 + gid) * SB + kk]);
                bb[g][1] = *reinterpret_cast<const uint32_t*>(&sm[B_OFF + (n0 + gid) * SB + kk + 8]);
            }
#pragma unroll
            for (int f = 0; f < 2; f++)
#pragma unroll
                for (int g = 0; g < 4; g++)
                    mma16816(c[f][g], a[f], bb[g]);
        }
    }

    // ---- epilogue -> fp16 hidden ----
#pragma unroll
    for (int f = 0; f < 2; f++) {
#pragma unroll
        for (int g = 0; g < 4; g++) {
            int row = blockM + wm * 32 + f * 16 + gid;
            int col = blockN + wn * 32 + g * 8 + 2 * tig;
            if (row < M)
                *reinterpret_cast<__half2*>(&hidden[(size_t)row * DIM + col]) =
                    __floats2half2_rn(c[f][g][0], c[f][g][1]);
            if (row + 8 < M)
                *reinterpret_cast<__half2*>(&hidden[(size_t)(row + 8) * DIM + col]) =
                    __floats2half2_rn(c[f][g][2], c[f][g][3]);
        }
    }
}

// ===========================================================================
// CSR build: histogram + 3-phase multi-block scan + scatter (packed int2)
// ===========================================================================
__global__ void hist_kernel(const int* __restrict__ rows, int* __restrict__ counts, int E) {
    int i = blockIdx.x * blockDim.x + threadIdx.x;
    if (i < E) atomicAdd(&counts[rows[i]], 1);
}

__device__ __forceinline__ int block_scan_inclusive(int v, int tid) {
    __shared__ int wsum[8];
    const int lane = tid & 31, wid = tid >> 5;
#pragma unroll
    for (int off = 1; off < 32; off <<= 1) {
        int n = __shfl_up_sync(0xffffffffu, v, off);
        if (lane >= off) v += n;
    }
    if (lane == 31) wsum[wid] = v;
    __syncthreads();
    if (wid == 0) {
        int s = (lane < 8) ? wsum[lane] : 0;
#pragma unroll
        for (int off = 1; off < 8; off <<= 1) {
            int n = __shfl_up_sync(0xffffffffu, s, off);
            if (lane >= off) s += n;
        }
        if (lane < 8) wsum[lane] = s;
    }
    __syncthreads();
    if (wid > 0) v += wsum[wid - 1];
    return v;
}

__global__ __launch_bounds__(256) void scan_partial_kernel(const int* __restrict__ counts,
                                                           int* __restrict__ partials, int M) {
    __shared__ int wsum[8];
    int i = blockIdx.x * 256 + threadIdx.x;
    int v = (i < M) ? counts[i] : 0;
    const int lane = threadIdx.x & 31, wid = threadIdx.x >> 5;
#pragma unroll
    for (int off = 16; off > 0; off >>= 1) v += __shfl_down_sync(0xffffffffu, v, off);
    if (lane == 0) wsum[wid] = v;
    __syncthreads();
    if (threadIdx.x == 0) {
        int s = 0;
#pragma unroll
        for (int k = 0; k < 8; k++) s += wsum[k];
        partials[blockIdx.x] = s;
    }
}

__global__ __launch_bounds__(256) void scan_offsets_kernel(int* __restrict__ partials, int NB) {
    int t = threadIdx.x;
    int v = (t < NB) ? partials[t] : 0;
    int incl = block_scan_inclusive(v, t);
    if (t < NB) partials[t] = incl - v;
}

__global__ __launch_bounds__(256) void scan_final_kernel(const int* __restrict__ counts,
                                                         const int* __restrict__ partials,
                                                         int* __restrict__ row_ptr,
                                                         int* __restrict__ cursor,
                                                         int M, int E) {
    int i = blockIdx.x * 256 + threadIdx.x;
    int v = (i < M) ? counts[i] : 0;
    int incl = block_scan_inclusive(v, threadIdx.x);
    int excl = incl - v + partials[blockIdx.x];
    if (i < M) {
        row_ptr[i] = excl;
        cursor[i]  = excl;
    }
    if (i == 0) row_ptr[M] = E;
}

__global__ void scatter_kernel(const int* __restrict__ rows,
                               const int* __restrict__ cols,
                               const float* __restrict__ vals,
                               int*  __restrict__ cursor,
                               int2* __restrict__ csr_pack,
                               int E) {
    int i = blockIdx.x * blockDim.x + threadIdx.x;
    if (i < E) {
        int r   = rows[i];
        int pos = atomicAdd(&cursor[r], 1);
        csr_pack[pos] = make_int2(cols[i], __float_as_int(vals[i]));
    }
}

// ===========================================================================
// SpMM: warp per dest row, fp16 hidden, packed CSR, 4-edge unroll.
// Per edge: 1 uniform LDG.64 (same addr all lanes) + 1 LDG.128 gather.
// ===========================================================================
__device__ __forceinline__ void fma8_half(float* acc, uint4 r, float v) {
    float2 f0 = __half22float2(*reinterpret_cast<__half2*>(&r.x));
    float2 f1 = __half22float2(*reinterpret_cast<__half2*>(&r.y));
    float2 f2 = __half22float2(*reinterpret_cast<__half2*>(&r.z));
    float2 f3 = __half22float2(*reinterpret_cast<__half2*>(&r.w));
    acc[0] = fmaf(v, f0.x, acc[0]); acc[1] = fmaf(v, f0.y, acc[1]);
    acc[2] = fmaf(v, f1.x, acc[2]); acc[3] = fmaf(v, f1.y, acc[3]);
    acc[4] = fmaf(v, f2.x, acc[4]); acc[5] = fmaf(v, f2.y, acc[5]);
    acc[6] = fmaf(v, f3.x, acc[6]); acc[7] = fmaf(v, f3.y, acc[7]);
}

__global__ __launch_bounds__(256) void spmm_warp_kernel(const int*  __restrict__ row_ptr,
                                                        const int2* __restrict__ csr_pack,
                                                        const __half* __restrict__ hidden,
                                                        const float* __restrict__ b,
                                                        float*       __restrict__ out,
                                                        int M) {
    const int w    = (blockIdx.x * blockDim.x + threadIdx.x) >> 5;
    const int lane = threadIdx.x & 31;
    if (w >= M) return;

    const int s = row_ptr[w];
    const int e = row_ptr[w + 1];

    float acc[8];
#pragma unroll
    for (int q = 0; q < 8; q++) acc[q] = 0.f;

    int j = s;
    for (; j + 3 < e; j += 4) {
        int2 p0 = csr_pack[j];
        int2 p1 = csr_pack[j + 1];
        int2 p2 = csr_pack[j + 2];
        int2 p3 = csr_pack[j + 3];
        uint4 r0 = reinterpret_cast<const uint4*>(hidden + (size_t)p0.x * DIM)[lane];
        uint4 r1 = reinterpret_cast<const uint4*>(hidden + (size_t)p1.x * DIM)[lane];
        uint4 r2 = reinterpret_cast<const uint4*>(hidden + (size_t)p2.x * DIM)[lane];
        uint4 r3 = reinterpret_cast<const uint4*>(hidden + (size_t)p3.x * DIM)[lane];
        fma8_half(acc, r0, __int_as_float(p0.y));
        fma8_half(acc, r1, __int_as_float(p1.y));
        fma8_half(acc, r2, __int_as_float(p2.y));
        fma8_half(acc, r3, __int_as_float(p3.y));
    }
    for (; j < e; j++) {
        int2 p0 = csr_pack[j];
        uint4 r0 = reinterpret_cast<const uint4*>(hidden + (size_t)p0.x * DIM)[lane];
        fma8_half(acc, r0, __int_as_float(p0.y));
    }

    const float4* b4 = reinterpret_cast<const float4*>(b + lane * 8);
    float4 bb0 = b4[0], bb1 = b4[1];
    float4* o = reinterpret_cast<float4*>(out + (size_t)w * DIM + lane * 8);
    o[0] = make_float4(acc[0] + bb0.x, acc[1] + bb0.y, acc[2] + bb0.z, acc[3] + bb0.w);
    o[1] = make_float4(acc[4] + bb1.x, acc[5] + bb1.y, acc[6] + bb1.z, acc[7] + bb1.w);
}

// ===========================================================================
// Launch — GEMM branch || CSR branch, join before SpMM.
// ===========================================================================
extern "C" void kernel_launch(void* const* d_in, const int* in_sizes, int n_in,
                              void* d_out, int out_size) {
    const float* x        = (const float*)d_in[0];
    const int*   adj_rows = (const int*)  d_in[1];
    const int*   adj_cols = (const int*)  d_in[2];
    const float* adj_vals = (const float*)d_in[3];
    const float* W        = (const float*)d_in[4];
    const float* b        = (const float*)d_in[5];
    float*       out      = (float*)d_out;

    const int M = in_sizes[0] / DIM;   // 50000
    const int E = in_sizes[1];         // 800000

    __half *hidden, *wt;
    int *counts, *partials, *row_ptr, *cursor;
    int2 *csr_pack;
    cudaGetSymbolAddress((void**)&hidden,   g_hidden_h);
    cudaGetSymbolAddress((void**)&wt,       g_WT);
    cudaGetSymbolAddress((void**)&counts,   g_counts);
    cudaGetSymbolAddress((void**)&partials, g_partials);
    cudaGetSymbolAddress((void**)&row_ptr,  g_row_ptr);
    cudaGetSymbolAddress((void**)&cursor,   g_cursor);
    cudaGetSymbolAddress((void**)&csr_pack, g_csr_pack);

    const int NB = (M + 255) / 256;

    static cudaStream_t s_csr = nullptr;
    static cudaEvent_t  ev_fork = nullptr, ev_join = nullptr;
    if (s_csr == nullptr) {
        cudaStreamCreateWithFlags(&s_csr, cudaStreamNonBlocking);
        cudaEventCreateWithFlags(&ev_fork, cudaEventDisableTiming);
        cudaEventCreateWithFlags(&ev_join, cudaEventDisableTiming);
        cudaFuncSetAttribute(gemm_mma_kernel,
                             cudaFuncAttributeMaxDynamicSharedMemorySize, GEMM_SMEM_BYTES);
    }

    // ---- fork: CSR branch ----
    cudaEventRecord(ev_fork, 0);
    cudaStreamWaitEvent(s_csr, ev_fork, 0);

    cudaMemsetAsync(counts, 0, (size_t)M * sizeof(int), s_csr);
    hist_kernel<<<(E + 255) / 256, 256, 0, s_csr>>>(adj_rows, counts, E);
    scan_partial_kernel<<<NB, 256, 0, s_csr>>>(counts, partials, M);
    scan_offsets_kernel<<<1, 256, 0, s_csr>>>(partials, NB);
    scan_final_kernel<<<NB, 256, 0, s_csr>>>(counts, partials, row_ptr, cursor, M, E);
    scatter_kernel<<<(E + 255) / 256, 256, 0, s_csr>>>(adj_rows, adj_cols, adj_vals,
                                                       cursor, csr_pack, E);
    cudaEventRecord(ev_join, s_csr);

    // ---- GEMM branch ----
    wt_convert_kernel<<<DIM, DIM>>>(W, wt);
    dim3 gemmGrid(DIM / 64, (M + 127) / 128);
    gemm_mma_kernel<<<gemmGrid, 256, GEMM_SMEM_BYTES>>>(x, wt, hidden, M);

    // ---- join, then SpMM ----
    cudaStreamWaitEvent(0, ev_join, 0);
    spmm_warp_kernel<<<(M * 32 + 255) / 256, 256>>>(row_ptr, csr_pack, hidden, b, out, M);
}

// round 8
// speedup vs baseline: 10.3892x; 1.0018x over previous
#include <cuda_runtime.h>
#include <cuda_bf16.h>
#include <cuda_fp16.h>
#include <cstdint>

#define DIM 256
#define N_NODES_MAX 50000
#define N_EDGES_MAX 800000
#define SCAN_NB ((N_NODES_MAX + 255) / 256)   // 196

// ----- scratch (__device__ globals; no cudaMalloc allowed) -----
__device__ __half         g_hidden_h[N_NODES_MAX * DIM]; // x @ W (fp16)
__device__ __half         g_WT[DIM * DIM];               // W^T fp16 (WT[n][k])
__device__ int            g_counts[N_NODES_MAX];
__device__ int            g_partials[SCAN_NB];
__device__ int            g_row_ptr[N_NODES_MAX + 1];
__device__ int            g_cursor[N_NODES_MAX];
__device__ int2           g_csr_pack[N_EDGES_MAX];       // (col, val-bits)

// ===========================================================================
// Kernel 0: W^T fp16.  WT[n][k] = W[k][n]
// ===========================================================================
__global__ void wt_convert_kernel(const float* __restrict__ W,
                                  __half* __restrict__ wt) {
    int k = blockIdx.x;
    int n = threadIdx.x;
    wt[n * DIM + k] = __float2half_rn(W[k * DIM + n]);
}

// ===========================================================================
// Kernel 1: mma.sync fp16 GEMM over an N-column half (n_base in 64-blocks).
// Block 256 thr = 8 warps (4Mx2N), tile 128x64, warp tile 32x32, fp32 accum.
// ===========================================================================
#define SA 72     // A smem row stride (64 + 8 pad) in halves
#define SB 264    // B smem row stride (256 + 8 pad) in halves
#define A_OFF 0
#define B_OFF (128 * SA)
#define GEMM_SMEM_BYTES ((128 * SA + 64 * SB) * 2)   // 52224

__device__ __forceinline__ void mma16816(float* c, const uint32_t* a, const uint32_t* b) {
    asm volatile(
        "mma.sync.aligned.m16n8k16.row.col.f32.f16.f16.f32 "
        "{%0,%1,%2,%3}, {%4,%5,%6,%7}, {%8,%9}, {%0,%1,%2,%3};"
        : "+f"(c[0]), "+f"(c[1]), "+f"(c[2]), "+f"(c[3])
        : "r"(a[0]), "r"(a[1]), "r"(a[2]), "r"(a[3]), "r"(b[0]), "r"(b[1]));
}

__global__ __launch_bounds__(256, 2) void gemm_mma_kernel(
        const float* __restrict__ x,
        const __half* __restrict__ wt,
        __half* __restrict__ hidden, int M, int n_base) {
    extern __shared__ __half sm[];

    const int tid  = threadIdx.x;
    const int warp = tid >> 5;
    const int lane = tid & 31;
    const int gid  = lane >> 2;
    const int tig  = lane & 3;
    const int wm   = warp >> 1;
    const int wn   = warp & 1;
    const int blockM = blockIdx.y * 128;
    const int blockN = (blockIdx.x + n_base) * 64;

    // ---- load B tile (full K): 64 rows x 256 k ----
#pragma unroll
    for (int t = 0; t < 8; t++) {
        int idx = tid + t * 256;          // 0..2047
        int n = idx >> 5;
        int j = idx & 31;
        *reinterpret_cast<uint4*>(&sm[B_OFF + n * SB + j * 8]) =
            *reinterpret_cast<const uint4*>(&wt[(size_t)(blockN + n) * DIM + j * 8]);
    }

    float c[2][4][4];
#pragma unroll
    for (int f = 0; f < 2; f++)
#pragma unroll
        for (int g = 0; g < 4; g++)
#pragma unroll
            for (int q = 0; q < 4; q++) c[f][g][q] = 0.f;

    for (int kc = 0; kc < 4; kc++) {
        __syncthreads();
#pragma unroll
        for (int t = 0; t < 8; t++) {
            int idx = tid + t * 256;
            int row = idx >> 4;
            int c4  = idx & 15;
            float4 v = make_float4(0.f, 0.f, 0.f, 0.f);
            if (blockM + row < M)
                v = *reinterpret_cast<const float4*>(
                        &x[(size_t)(blockM + row) * DIM + kc * 64 + c4 * 4]);
            __half2 p0 = __floats2half2_rn(v.x, v.y);
            __half2 p1 = __floats2half2_rn(v.z, v.w);
            *reinterpret_cast<uint2*>(&sm[A_OFF + row * SA + c4 * 4]) =
                make_uint2(*reinterpret_cast<uint32_t*>(&p0),
                           *reinterpret_cast<uint32_t*>(&p1));
        }
        __syncthreads();

#pragma unroll
        for (int ks = 0; ks < 4; ks++) {
            const int kb = ks * 16;
            uint32_t a[2][4], bb[4][2];
#pragma unroll
            for (int f = 0; f < 2; f++) {
                int r0 = wm * 32 + f * 16;
                a[f][0] = *reinterpret_cast<const uint32_t*>(&sm[A_OFF + (r0 + gid)     * SA + kb + 2 * tig]);
                a[f][1] = *reinterpret_cast<const uint32_t*>(&sm[A_OFF + (r0 + gid + 8) * SA + kb + 2 * tig]);
                a[f][2] = *reinterpret_cast<const uint32_t*>(&sm[A_OFF + (r0 + gid)     * SA + kb + 2 * tig + 8]);
                a[f][3] = *reinterpret_cast<const uint32_t*>(&sm[A_OFF + (r0 + gid + 8) * SA + kb + 2 * tig + 8]);
            }
#pragma unroll
            for (int g = 0; g < 4; g++) {
                int n0 = wn * 32 + g * 8;
                int kk = kc * 64 + kb + 2 * tig;
                bb[g][0] = *reinterpret_cast<const uint32_t*>(&sm[B_OFF + (n0 + gid) * SB + kk]);
                bb[g][1] = *reinterpret_cast<const uint32_t*>(&sm[B_OFF + (n0 + gid) * SB + kk + 8]);
            }
#pragma unroll
            for (int f = 0; f < 2; f++)
#pragma unroll
                for (int g = 0; g < 4; g++)
                    mma16816(c[f][g], a[f], bb[g]);
        }
    }

#pragma unroll
    for (int f = 0; f < 2; f++) {
#pragma unroll
        for (int g = 0; g < 4; g++) {
            int row = blockM + wm * 32 + f * 16 + gid;
            int col = blockN + wn * 32 + g * 8 + 2 * tig;
            if (row < M)
                *reinterpret_cast<__half2*>(&hidden[(size_t)row * DIM + col]) =
                    __floats2half2_rn(c[f][g][0], c[f][g][1]);
            if (row + 8 < M)
                *reinterpret_cast<__half2*>(&hidden[(size_t)(row + 8) * DIM + col]) =
                    __floats2half2_rn(c[f][g][2], c[f][g][3]);
        }
    }
}

// ===========================================================================
// CSR build: histogram + 3-phase multi-block scan + scatter (packed int2)
// ===========================================================================
__global__ void hist_kernel(const int* __restrict__ rows, int* __restrict__ counts, int E) {
    int i = blockIdx.x * blockDim.x + threadIdx.x;
    if (i < E) atomicAdd(&counts[rows[i]], 1);
}

__device__ __forceinline__ int block_scan_inclusive(int v, int tid) {
    __shared__ int wsum[8];
    const int lane = tid & 31, wid = tid >> 5;
#pragma unroll
    for (int off = 1; off < 32; off <<= 1) {
        int n = __shfl_up_sync(0xffffffffu, v, off);
        if (lane >= off) v += n;
    }
    if (lane == 31) wsum[wid] = v;
    __syncthreads();
    if (wid == 0) {
        int s = (lane < 8) ? wsum[lane] : 0;
#pragma unroll
        for (int off = 1; off < 8; off <<= 1) {
            int n = __shfl_up_sync(0xffffffffu, s, off);
            if (lane >= off) s += n;
        }
        if (lane < 8) wsum[lane] = s;
    }
    __syncthreads();
    if (wid > 0) v += wsum[wid - 1];
    return v;
}

__global__ __launch_bounds__(256) void scan_partial_kernel(const int* __restrict__ counts,
                                                           int* __restrict__ partials, int M) {
    __shared__ int wsum[8];
    int i = blockIdx.x * 256 + threadIdx.x;
    int v = (i < M) ? counts[i] : 0;
    const int lane = threadIdx.x & 31, wid = threadIdx.x >> 5;
#pragma unroll
    for (int off = 16; off > 0; off >>= 1) v += __shfl_down_sync(0xffffffffu, v, off);
    if (lane == 0) wsum[wid] = v;
    __syncthreads();
    if (threadIdx.x == 0) {
        int s = 0;
#pragma unroll
        for (int k = 0; k < 8; k++) s += wsum[k];
        partials[blockIdx.x] = s;
    }
}

__global__ __launch_bounds__(256) void scan_offsets_kernel(int* __restrict__ partials, int NB) {
    int t = threadIdx.x;
    int v = (t < NB) ? partials[t] : 0;
    int incl = block_scan_inclusive(v, t);
    if (t < NB) partials[t] = incl - v;
}

__global__ __launch_bounds__(256) void scan_final_kernel(const int* __restrict__ counts,
                                                         const int* __restrict__ partials,
                                                         int* __restrict__ row_ptr,
                                                         int* __restrict__ cursor,
                                                         int M, int E) {
    int i = blockIdx.x * 256 + threadIdx.x;
    int v = (i < M) ? counts[i] : 0;
    int incl = block_scan_inclusive(v, threadIdx.x);
    int excl = incl - v + partials[blockIdx.x];
    if (i < M) {
        row_ptr[i] = excl;
        cursor[i]  = excl;
    }
    if (i == 0) row_ptr[M] = E;
}

__global__ void scatter_kernel(const int* __restrict__ rows,
                               const int* __restrict__ cols,
                               const float* __restrict__ vals,
                               int*  __restrict__ cursor,
                               int2* __restrict__ csr_pack,
                               int E) {
    int i = blockIdx.x * blockDim.x + threadIdx.x;
    if (i < E) {
        int r   = rows[i];
        int pos = atomicAdd(&cursor[r], 1);
        csr_pack[pos] = make_int2(cols[i], __float_as_int(vals[i]));
    }
}

// ===========================================================================
// SpMM over a 128-dim column half: warp per dest row, lane owns 4 dims
// (one LDG.64 gather per edge), 8-edge unroll => MLP=8 per lane.
// ===========================================================================
__device__ __forceinline__ void fma4_half(float* acc, uint2 r, float v) {
    float2 f0 = __half22float2(*reinterpret_cast<__half2*>(&r.x));
    float2 f1 = __half22float2(*reinterpret_cast<__half2*>(&r.y));
    acc[0] = fmaf(v, f0.x, acc[0]); acc[1] = fmaf(v, f0.y, acc[1]);
    acc[2] = fmaf(v, f1.x, acc[2]); acc[3] = fmaf(v, f1.y, acc[3]);
}

__global__ __launch_bounds__(256) void spmm_half_kernel(const int*  __restrict__ row_ptr,
                                                        const int2* __restrict__ csr_pack,
                                                        const __half* __restrict__ hidden,
                                                        const float* __restrict__ b,
                                                        float*       __restrict__ out,
                                                        int M, int colOff) {
    const int w    = (blockIdx.x * blockDim.x + threadIdx.x) >> 5;
    const int lane = threadIdx.x & 31;
    if (w >= M) return;

    const int s = row_ptr[w];
    const int e = row_ptr[w + 1];

    float acc[4] = {0.f, 0.f, 0.f, 0.f};
    const __half* hbase = hidden + colOff + lane * 4;

    int j = s;
    for (; j + 7 < e; j += 8) {
        int2 p[8];
#pragma unroll
        for (int q = 0; q < 8; q++) p[q] = csr_pack[j + q];
        uint2 r[8];
#pragma unroll
        for (int q = 0; q < 8; q++)
            r[q] = *reinterpret_cast<const uint2*>(hbase + (size_t)p[q].x * DIM);
#pragma unroll
        for (int q = 0; q < 8; q++)
            fma4_half(acc, r[q], __int_as_float(p[q].y));
    }
    for (; j < e; j++) {
        int2 p0 = csr_pack[j];
        uint2 r0 = *reinterpret_cast<const uint2*>(hbase + (size_t)p0.x * DIM);
        fma4_half(acc, r0, __int_as_float(p0.y));
    }

    float4 bb = *reinterpret_cast<const float4*>(b + colOff + lane * 4);
    *reinterpret_cast<float4*>(out + (size_t)w * DIM + colOff + lane * 4) =
        make_float4(acc[0] + bb.x, acc[1] + bb.y, acc[2] + bb.z, acc[3] + bb.w);
}

// ===========================================================================
// Launch — software pipeline:
//   default: wt -> gemm(cols 0-127) -> gemm(cols 128-255) -> spmm(128-255) -> join
//   s_csr  : memset -> hist -> scan -> scatter
//   s_aux  : spmm(cols 0-127)  [waits gemm half0 + CSR; runs || gemm half1]
// ===========================================================================
extern "C" void kernel_launch(void* const* d_in, const int* in_sizes, int n_in,
                              void* d_out, int out_size) {
    const float* x        = (const float*)d_in[0];
    const int*   adj_rows = (const int*)  d_in[1];
    const int*   adj_cols = (const int*)  d_in[2];
    const float* adj_vals = (const float*)d_in[3];
    const float* W        = (const float*)d_in[4];
    const float* b        = (const float*)d_in[5];
    float*       out      = (float*)d_out;

    const int M = in_sizes[0] / DIM;   // 50000
    const int E = in_sizes[1];         // 800000

    __half *hidden, *wt;
    int *counts, *partials, *row_ptr, *cursor;
    int2 *csr_pack;
    cudaGetSymbolAddress((void**)&hidden,   g_hidden_h);
    cudaGetSymbolAddress((void**)&wt,       g_WT);
    cudaGetSymbolAddress((void**)&counts,   g_counts);
    cudaGetSymbolAddress((void**)&partials, g_partials);
    cudaGetSymbolAddress((void**)&row_ptr,  g_row_ptr);
    cudaGetSymbolAddress((void**)&cursor,   g_cursor);
    cudaGetSymbolAddress((void**)&csr_pack, g_csr_pack);

    const int NB = (M + 255) / 256;

    static cudaStream_t s_csr = nullptr, s_aux = nullptr;
    static cudaEvent_t  ev_fork = nullptr, ev_csr = nullptr, ev_g0 = nullptr, ev_sp0 = nullptr;
    if (s_csr == nullptr) {
        cudaStreamCreateWithFlags(&s_csr, cudaStreamNonBlocking);
        cudaStreamCreateWithFlags(&s_aux, cudaStreamNonBlocking);
        cudaEventCreateWithFlags(&ev_fork, cudaEventDisableTiming);
        cudaEventCreateWithFlags(&ev_csr,  cudaEventDisableTiming);
        cudaEventCreateWithFlags(&ev_g0,   cudaEventDisableTiming);
        cudaEventCreateWithFlags(&ev_sp0,  cudaEventDisableTiming);
        cudaFuncSetAttribute(gemm_mma_kernel,
                             cudaFuncAttributeMaxDynamicSharedMemorySize, GEMM_SMEM_BYTES);
    }

    const int spmmBlocks = (M * 32 + 255) / 256;

    // ---- fork: CSR branch on s_csr ----
    cudaEventRecord(ev_fork, 0);
    cudaStreamWaitEvent(s_csr, ev_fork, 0);

    cudaMemsetAsync(counts, 0, (size_t)M * sizeof(int), s_csr);
    hist_kernel<<<(E + 255) / 256, 256, 0, s_csr>>>(adj_rows, counts, E);
    scan_partial_kernel<<<NB, 256, 0, s_csr>>>(counts, partials, M);
    scan_offsets_kernel<<<1, 256, 0, s_csr>>>(partials, NB);
    scan_final_kernel<<<NB, 256, 0, s_csr>>>(counts, partials, row_ptr, cursor, M, E);
    scatter_kernel<<<(E + 255) / 256, 256, 0, s_csr>>>(adj_rows, adj_cols, adj_vals,
                                                       cursor, csr_pack, E);
    cudaEventRecord(ev_csr, s_csr);

    // ---- GEMM half 0 (cols 0-127) ----
    wt_convert_kernel<<<DIM, DIM>>>(W, wt);
    dim3 gemmGrid(2, (M + 127) / 128);
    gemm_mma_kernel<<<gemmGrid, 256, GEMM_SMEM_BYTES>>>(x, wt, hidden, M, 0);
    cudaEventRecord(ev_g0, 0);

    // ---- GEMM half 1 (cols 128-255) on default stream ----
    gemm_mma_kernel<<<gemmGrid, 256, GEMM_SMEM_BYTES>>>(x, wt, hidden, M, 2);

    // ---- SpMM half 0 on s_aux: needs gemm half0 + CSR; overlaps gemm half1 ----
    cudaStreamWaitEvent(s_aux, ev_g0, 0);
    cudaStreamWaitEvent(s_aux, ev_csr, 0);
    spmm_half_kernel<<<spmmBlocks, 256, 0, s_aux>>>(row_ptr, csr_pack, hidden, b, out, M, 0);
    cudaEventRecord(ev_sp0, s_aux);

    // ---- SpMM half 1 on default (after gemm half1; needs CSR too) ----
    cudaStreamWaitEvent(0, ev_csr, 0);
    spmm_half_kernel<<<spmmBlocks, 256>>>(row_ptr, csr_pack, hidden, b, out, M, 128);

    // ---- join ----
    cudaStreamWaitEvent(0, ev_sp0, 0);
}

// round 9
// speedup vs baseline: 10.7931x; 1.0389x over previous
#include <cuda_runtime.h>
#include <cuda_bf16.h>
#include <cuda_fp16.h>
#include <cstdint>

#define DIM 256
#define N_NODES_MAX 50000
#define N_EDGES_MAX 800000
#define ELLW 96              // ELL row width (avg degree 16; P(>96) ~ 0)
#define OVF_CAP 4096

// ----- scratch (__device__ globals; no cudaMalloc allowed) -----
__device__ __half  g_hidden_h[N_NODES_MAX * DIM];     // x @ W (fp16)
__device__ __half  g_WT[DIM * DIM];                   // W^T fp16 (WT[n][k])
__device__ int     g_counts[N_NODES_MAX];             // per-row edge counts
__device__ int2    g_ell[(size_t)N_NODES_MAX * ELLW]; // (col, val-bits) per slot
__device__ int     g_ovf_cnt[1];
__device__ int4    g_ovf[OVF_CAP];                    // (row, col, val-bits, _)

// ===========================================================================
// Kernel 0: W^T fp16.  WT[n][k] = W[k][n]
// ===========================================================================
__global__ void wt_convert_kernel(const float* __restrict__ W,
                                  __half* __restrict__ wt) {
    int k = blockIdx.x;
    int n = threadIdx.x;
    wt[n * DIM + k] = __float2half_rn(W[k * DIM + n]);
}

// ===========================================================================
// Kernel 1: mma.sync fp16 GEMM over an N-column half (n_base in 64-blocks).
// ===========================================================================
#define SA 72
#define SB 264
#define A_OFF 0
#define B_OFF (128 * SA)
#define GEMM_SMEM_BYTES ((128 * SA + 64 * SB) * 2)   // 52224

__device__ __forceinline__ void mma16816(float* c, const uint32_t* a, const uint32_t* b) {
    asm volatile(
        "mma.sync.aligned.m16n8k16.row.col.f32.f16.f16.f32 "
        "{%0,%1,%2,%3}, {%4,%5,%6,%7}, {%8,%9}, {%0,%1,%2,%3};"
        : "+f"(c[0]), "+f"(c[1]), "+f"(c[2]), "+f"(c[3])
        : "r"(a[0]), "r"(a[1]), "r"(a[2]), "r"(a[3]), "r"(b[0]), "r"(b[1]));
}

__global__ __launch_bounds__(256, 2) void gemm_mma_kernel(
        const float* __restrict__ x,
        const __half* __restrict__ wt,
        __half* __restrict__ hidden, int M, int n_base) {
    extern __shared__ __half sm[];

    const int tid  = threadIdx.x;
    const int warp = tid >> 5;
    const int lane = tid & 31;
    const int gid  = lane >> 2;
    const int tig  = lane & 3;
    const int wm   = warp >> 1;
    const int wn   = warp & 1;
    const int blockM = blockIdx.y * 128;
    const int blockN = (blockIdx.x + n_base) * 64;

#pragma unroll
    for (int t = 0; t < 8; t++) {
        int idx = tid + t * 256;
        int n = idx >> 5;
        int j = idx & 31;
        *reinterpret_cast<uint4*>(&sm[B_OFF + n * SB + j * 8]) =
            *reinterpret_cast<const uint4*>(&wt[(size_t)(blockN + n) * DIM + j * 8]);
    }

    float c[2][4][4];
#pragma unroll
    for (int f = 0; f < 2; f++)
#pragma unroll
        for (int g = 0; g < 4; g++)
#pragma unroll
            for (int q = 0; q < 4; q++) c[f][g][q] = 0.f;

    for (int kc = 0; kc < 4; kc++) {
        __syncthreads();
#pragma unroll
        for (int t = 0; t < 8; t++) {
            int idx = tid + t * 256;
            int row = idx >> 4;
            int c4  = idx & 15;
            float4 v = make_float4(0.f, 0.f, 0.f, 0.f);
            if (blockM + row < M)
                v = *reinterpret_cast<const float4*>(
                        &x[(size_t)(blockM + row) * DIM + kc * 64 + c4 * 4]);
            __half2 p0 = __floats2half2_rn(v.x, v.y);
            __half2 p1 = __floats2half2_rn(v.z, v.w);
            *reinterpret_cast<uint2*>(&sm[A_OFF + row * SA + c4 * 4]) =
                make_uint2(*reinterpret_cast<uint32_t*>(&p0),
                           *reinterpret_cast<uint32_t*>(&p1));
        }
        __syncthreads();

#pragma unroll
        for (int ks = 0; ks < 4; ks++) {
            const int kb = ks * 16;
            uint32_t a[2][4], bb[4][2];
#pragma unroll
            for (int f = 0; f < 2; f++) {
                int r0 = wm * 32 + f * 16;
                a[f][0] = *reinterpret_cast<const uint32_t*>(&sm[A_OFF + (r0 + gid)     * SA + kb + 2 * tig]);
                a[f][1] = *reinterpret_cast<const uint32_t*>(&sm[A_OFF + (r0 + gid + 8) * SA + kb + 2 * tig]);
                a[f][2] = *reinterpret_cast<const uint32_t*>(&sm[A_OFF + (r0 + gid)     * SA + kb + 2 * tig + 8]);
                a[f][3] = *reinterpret_cast<const uint32_t*>(&sm[A_OFF + (r0 + gid + 8) * SA + kb + 2 * tig + 8]);
            }
#pragma unroll
            for (int g = 0; g < 4; g++) {
                int n0 = wn * 32 + g * 8;
                int kk = kc * 64 + kb + 2 * tig;
                bb[g][0] = *reinterpret_cast<const uint32_t*>(&sm[B_OFF + (n0 + gid) * SB + kk]);
                bb[g][1] = *reinterpret_cast<const uint32_t*>(&sm[B_OFF + (n0 + gid) * SB + kk + 8]);
            }
#pragma unroll
            for (int f = 0; f < 2; f++)
#pragma unroll
                for (int g = 0; g < 4; g++)
                    mma16816(c[f][g], a[f], bb[g]);
        }
    }

#pragma unroll
    for (int f = 0; f < 2; f++) {
#pragma unroll
        for (int g = 0; g < 4; g++) {
            int row = blockM + wm * 32 + f * 16 + gid;
            int col = blockN + wn * 32 + g * 8 + 2 * tig;
            if (row < M)
                *reinterpret_cast<__half2*>(&hidden[(size_t)row * DIM + col]) =
                    __floats2half2_rn(c[f][g][0], c[f][g][1]);
            if (row + 8 < M)
                *reinterpret_cast<__half2*>(&hidden[(size_t)(row + 8) * DIM + col]) =
                    __floats2half2_rn(c[f][g][2], c[f][g][3]);
        }
    }
}

// ===========================================================================
// ELL build: ONE scatter kernel (no hist, no scan).
// pos = atomicAdd(counts[r]); slot r*ELLW+pos. Overflow -> capped side list.
// ===========================================================================
__global__ void ell_scatter_kernel(const int* __restrict__ rows,
                                   const int* __restrict__ cols,
                                   const float* __restrict__ vals,
                                   int*  __restrict__ counts,
                                   int2* __restrict__ ell,
                                   int*  __restrict__ ovf_cnt,
                                   int4* __restrict__ ovf,
                                   int E) {
    int i = blockIdx.x * blockDim.x + threadIdx.x;
    if (i < E) {
        int r   = rows[i];
        int pos = atomicAdd(&counts[r], 1);
        if (pos < ELLW) {
            ell[(size_t)r * ELLW + pos] = make_int2(cols[i], __float_as_int(vals[i]));
        } else {
            int o = atomicAdd(ovf_cnt, 1);
            if (o < OVF_CAP)
                ovf[o] = make_int4(r, cols[i], __float_as_int(vals[i]), 0);
        }
    }
}

// ===========================================================================
// SpMM over a 128-dim column half: warp per dest row, lane owns 4 dims
// (one LDG.64 gather per edge), 8-edge unroll => MLP=8 per lane.
// ===========================================================================
__device__ __forceinline__ void fma4_half(float* acc, uint2 r, float v) {
    float2 f0 = __half22float2(*reinterpret_cast<__half2*>(&r.x));
    float2 f1 = __half22float2(*reinterpret_cast<__half2*>(&r.y));
    acc[0] = fmaf(v, f0.x, acc[0]); acc[1] = fmaf(v, f0.y, acc[1]);
    acc[2] = fmaf(v, f1.x, acc[2]); acc[3] = fmaf(v, f1.y, acc[3]);
}

__global__ __launch_bounds__(256) void spmm_half_kernel(const int*  __restrict__ counts,
                                                        const int2* __restrict__ ell,
                                                        const __half* __restrict__ hidden,
                                                        const float* __restrict__ b,
                                                        float*       __restrict__ out,
                                                        int M, int colOff) {
    const int w    = (blockIdx.x * blockDim.x + threadIdx.x) >> 5;
    const int lane = threadIdx.x & 31;
    if (w >= M) return;

    const int cnt = min(counts[w], ELLW);
    const int2* erow = ell + (size_t)w * ELLW;

    float acc[4] = {0.f, 0.f, 0.f, 0.f};
    const __half* hbase = hidden + colOff + lane * 4;

    int j = 0;
    for (; j + 7 < cnt; j += 8) {
        int2 p[8];
#pragma unroll
        for (int q = 0; q < 8; q++) p[q] = erow[j + q];
        uint2 r[8];
#pragma unroll
        for (int q = 0; q < 8; q++)
            r[q] = *reinterpret_cast<const uint2*>(hbase + (size_t)p[q].x * DIM);
#pragma unroll
        for (int q = 0; q < 8; q++)
            fma4_half(acc, r[q], __int_as_float(p[q].y));
    }
    for (; j < cnt; j++) {
        int2 p0 = erow[j];
        uint2 r0 = *reinterpret_cast<const uint2*>(hbase + (size_t)p0.x * DIM);
        fma4_half(acc, r0, __int_as_float(p0.y));
    }

    float4 bb = *reinterpret_cast<const float4*>(b + colOff + lane * 4);
    *reinterpret_cast<float4*>(out + (size_t)w * DIM + colOff + lane * 4) =
        make_float4(acc[0] + bb.x, acc[1] + bb.y, acc[2] + bb.z, acc[3] + bb.w);
}

// ===========================================================================
// Overflow fixup: normally n==0; loops serially, no atomics needed (runs
// after all SpMM writes; sole owner of out at that point).
// ===========================================================================
__global__ void ovf_fixup_kernel(const int* __restrict__ ovf_cnt,
                                 const int4* __restrict__ ovf,
                                 const __half* __restrict__ hidden,
                                 float* __restrict__ out) {
    int n = min(*ovf_cnt, OVF_CAP);
    int t = threadIdx.x;   // 256 threads, one per dim
    for (int e = 0; e < n; e++) {
        int4 p = ovf[e];
        float v = __int_as_float(p.z);
        out[(size_t)p.x * DIM + t] =
            fmaf(v, __half2float(hidden[(size_t)p.y * DIM + t]),
                 out[(size_t)p.x * DIM + t]);
    }
}

// ===========================================================================
// Launch — pipeline with the ELL build off the critical path:
//   s_csr  : memset counts/ovf -> ell_scatter                  (~22us)
//   default: wt -> gemm(cols 0-127) -> gemm(cols 128-255)
//   s_aux  : spmm(cols 0-127)   [after gemm0 + ELL; || gemm1]
//   default: spmm(cols 128-255) [after gemm1 + ELL] -> fixup -> join
// ===========================================================================
extern "C" void kernel_launch(void* const* d_in, const int* in_sizes, int n_in,
                              void* d_out, int out_size) {
    const float* x        = (const float*)d_in[0];
    const int*   adj_rows = (const int*)  d_in[1];
    const int*   adj_cols = (const int*)  d_in[2];
    const float* adj_vals = (const float*)d_in[3];
    const float* W        = (const float*)d_in[4];
    const float* b        = (const float*)d_in[5];
    float*       out      = (float*)d_out;

    const int M = in_sizes[0] / DIM;   // 50000
    const int E = in_sizes[1];         // 800000

    __half *hidden, *wt;
    int *counts, *ovf_cnt;
    int2 *ell;
    int4 *ovf;
    cudaGetSymbolAddress((void**)&hidden,  g_hidden_h);
    cudaGetSymbolAddress((void**)&wt,      g_WT);
    cudaGetSymbolAddress((void**)&counts,  g_counts);
    cudaGetSymbolAddress((void**)&ell,     g_ell);
    cudaGetSymbolAddress((void**)&ovf_cnt, g_ovf_cnt);
    cudaGetSymbolAddress((void**)&ovf,     g_ovf);

    static cudaStream_t s_csr = nullptr, s_aux = nullptr;
    static cudaEvent_t  ev_fork = nullptr, ev_csr = nullptr, ev_g0 = nullptr, ev_sp0 = nullptr;
    if (s_csr == nullptr) {
        cudaStreamCreateWithFlags(&s_csr, cudaStreamNonBlocking);
        cudaStreamCreateWithFlags(&s_aux, cudaStreamNonBlocking);
        cudaEventCreateWithFlags(&ev_fork, cudaEventDisableTiming);
        cudaEventCreateWithFlags(&ev_csr,  cudaEventDisableTiming);
        cudaEventCreateWithFlags(&ev_g0,   cudaEventDisableTiming);
        cudaEventCreateWithFlags(&ev_sp0,  cudaEventDisableTiming);
        cudaFuncSetAttribute(gemm_mma_kernel,
                             cudaFuncAttributeMaxDynamicSharedMemorySize, GEMM_SMEM_BYTES);
    }

    const int spmmBlocks = (M * 32 + 255) / 256;

    // ---- fork: ELL build on s_csr ----
    cudaEventRecord(ev_fork, 0);
    cudaStreamWaitEvent(s_csr, ev_fork, 0);

    cudaMemsetAsync(counts, 0, (size_t)M * sizeof(int), s_csr);
    cudaMemsetAsync(ovf_cnt, 0, sizeof(int), s_csr);
    ell_scatter_kernel<<<(E + 255) / 256, 256, 0, s_csr>>>(adj_rows, adj_cols, adj_vals,
                                                           counts, ell, ovf_cnt, ovf, E);
    cudaEventRecord(ev_csr, s_csr);

    // ---- GEMM half 0 (cols 0-127) ----
    wt_convert_kernel<<<DIM, DIM>>>(W, wt);
    dim3 gemmGrid(2, (M + 127) / 128);
    gemm_mma_kernel<<<gemmGrid, 256, GEMM_SMEM_BYTES>>>(x, wt, hidden, M, 0);
    cudaEventRecord(ev_g0, 0);

    // ---- GEMM half 1 (cols 128-255) ----
    gemm_mma_kernel<<<gemmGrid, 256, GEMM_SMEM_BYTES>>>(x, wt, hidden, M, 2);

    // ---- SpMM half 0 on s_aux: after gemm0 + ELL; overlaps gemm1 ----
    cudaStreamWaitEvent(s_aux, ev_g0, 0);
    cudaStreamWaitEvent(s_aux, ev_csr, 0);
    spmm_half_kernel<<<spmmBlocks, 256, 0, s_aux>>>(counts, ell, hidden, b, out, M, 0);
    cudaEventRecord(ev_sp0, s_aux);

    // ---- SpMM half 1 on default ----
    cudaStreamWaitEvent(0, ev_csr, 0);
    spmm_half_kernel<<<spmmBlocks, 256>>>(counts, ell, hidden, b, out, M, 128);

    // ---- overflow fixup (normally 0 edges), then join ----
    cudaStreamWaitEvent(0, ev_sp0, 0);
    ovf_fixup_kernel<<<1, 256>>>(ovf_cnt, ovf, hidden, out);
}